// round 1
// baseline (speedup 1.0000x reference)
#include <cuda_runtime.h>
#include <cuda_bf16.h>
#include <math.h>

// Problem constants
#define BB 32
#define TT 512
#define DD 512
#define EE 8
#define HH 2048

// Routing table + hidden-activation scratch (device globals: allocation-free)
__device__ int   g_expert[BB];
__device__ float g_h[(size_t)BB * TT * HH];   // 32*512*2048 floats = 128 MiB

// ---------------------------------------------------------------------------
// Router: pooled = mean_t x[b,t,:]; logits = pooled @ Wp + bp; softmax; argmax
// One block per utterance, 512 threads (one per feature d).
// ---------------------------------------------------------------------------
__global__ void router_kernel(const float* __restrict__ x,
                              const float* __restrict__ Wp,
                              const float* __restrict__ bp,
                              float* __restrict__ probs_out,   // [B, E]
                              float* __restrict__ expert_out)  // [B] (as float)
{
    const int b   = blockIdx.x;
    const int tid = threadIdx.x;       // 0..511

    __shared__ float pooled[DD];
    __shared__ float logits[EE];

    // mean over T for feature d = tid (coalesced across threads)
    float s = 0.f;
    const float* xb = x + (size_t)b * TT * DD + tid;
    #pragma unroll 4
    for (int t = 0; t < TT; ++t) s += xb[(size_t)t * DD];
    pooled[tid] = s * (1.0f / (float)TT);
    __syncthreads();

    // logits: warp w (w<8) computes expert w
    const int w = tid >> 5, lane = tid & 31;
    if (w < EE) {
        float acc = 0.f;
        for (int d = lane; d < DD; d += 32) acc += pooled[d] * Wp[d * EE + w];
        #pragma unroll
        for (int o = 16; o > 0; o >>= 1) acc += __shfl_down_sync(0xffffffffu, acc, o);
        if (lane == 0) logits[w] = acc + bp[w];
    }
    __syncthreads();

    if (tid == 0) {
        float m = logits[0]; int arg = 0;
        #pragma unroll
        for (int e = 1; e < EE; ++e) if (logits[e] > m) { m = logits[e]; arg = e; }
        float ex[EE]; float sum = 0.f;
        #pragma unroll
        for (int e = 0; e < EE; ++e) { ex[e] = expf(logits[e] - m); sum += ex[e]; }
        const float inv = 1.0f / sum;
        #pragma unroll
        for (int e = 0; e < EE; ++e) probs_out[b * EE + e] = ex[e] * inv;
        expert_out[b] = (float)arg;
        g_expert[b]   = arg;
    }
}

// ---------------------------------------------------------------------------
// Batched expert GEMM, 128x128 tile, BK=16, 8x8 per-thread, 256 threads.
//   C[b] = act(A[b] @ W[e_b] + bias[e_b])
// A is [512, K] row-major, W is [K, N] row-major, C is [512, N].
// Template flags choose whether A / C live in the g_h scratch.
// ---------------------------------------------------------------------------
template<int N, int K, bool RELU, bool A_FROM_H, bool C_TO_H>
__global__ __launch_bounds__(256)
void ffn_gemm(const float* __restrict__ Aext,
              const float* __restrict__ Wb,
              const float* __restrict__ bias,
              float* __restrict__ Cext)
{
    constexpr int BM = 128, BN = 128, BK = 16;
    constexpr int PAD = 4;                      // As row pad (keeps f4 alignment)

    const int b = blockIdx.z;
    const int e = g_expert[b];

    const float* A = (A_FROM_H ? g_h : Aext) + (size_t)b * TT * K;
    float*       C = (C_TO_H   ? g_h : Cext) + (size_t)b * TT * N;
    const float* W = Wb   + (size_t)e * K * N;
    const float* bv = bias + (size_t)e * N;

    const int tile_m = blockIdx.y * BM;
    const int tile_n = blockIdx.x * BN;

    __shared__ float As[BK][BM + PAD];   // transposed A tile: As[k][m]
    __shared__ float Bs[BK][BN];         // Bs[k][n]

    const int tid = threadIdx.x;          // 0..255
    const int tx  = tid & 15;             // n-tile lane  (8 cols each)
    const int ty  = tid >> 4;             // m-tile lane  (8 rows each)

    float acc[8][8];
    #pragma unroll
    for (int i = 0; i < 8; ++i)
        #pragma unroll
        for (int j = 0; j < 8; ++j) acc[i][j] = 0.f;

    const float* Ab = A + (size_t)tile_m * K;    // A tile base

    for (int kk = 0; kk < K; kk += BK) {
        // Load A tile (128 x 16), store transposed. 2 float4 per thread.
        #pragma unroll
        for (int i = 0; i < 2; ++i) {
            const int row = (tid >> 2) + i * 64;
            const int k4  = (tid & 3) * 4;
            float4 v = *(const float4*)(Ab + (size_t)row * K + kk + k4);
            As[k4 + 0][row] = v.x;
            As[k4 + 1][row] = v.y;
            As[k4 + 2][row] = v.z;
            As[k4 + 3][row] = v.w;
        }
        // Load B tile (16 x 128). 2 float4 per thread, contiguous stores.
        #pragma unroll
        for (int i = 0; i < 2; ++i) {
            const int krow = (tid >> 5) + i * 8;
            const int col4 = (tid & 31) * 4;
            *(float4*)&Bs[krow][col4] =
                *(const float4*)(W + (size_t)(kk + krow) * N + tile_n + col4);
        }
        __syncthreads();

        #pragma unroll
        for (int k = 0; k < BK; ++k) {
            float ra[8], rb[8];
            float4 a0 = *(const float4*)&As[k][ty * 8];
            float4 a1 = *(const float4*)&As[k][ty * 8 + 4];
            float4 b0 = *(const float4*)&Bs[k][tx * 8];
            float4 b1 = *(const float4*)&Bs[k][tx * 8 + 4];
            ra[0]=a0.x; ra[1]=a0.y; ra[2]=a0.z; ra[3]=a0.w;
            ra[4]=a1.x; ra[5]=a1.y; ra[6]=a1.z; ra[7]=a1.w;
            rb[0]=b0.x; rb[1]=b0.y; rb[2]=b0.z; rb[3]=b0.w;
            rb[4]=b1.x; rb[5]=b1.y; rb[6]=b1.z; rb[7]=b1.w;
            #pragma unroll
            for (int i = 0; i < 8; ++i)
                #pragma unroll
                for (int j = 0; j < 8; ++j)
                    acc[i][j] = fmaf(ra[i], rb[j], acc[i][j]);
        }
        __syncthreads();
    }

    // Epilogue: bias (+ ReLU), vectorized stores
    #pragma unroll
    for (int i = 0; i < 8; ++i) {
        const int row = tile_m + ty * 8 + i;
        float* crow = C + (size_t)row * N + tile_n + tx * 8;
        const float* brow = bv + tile_n + tx * 8;
        float4 v0, v1;
        v0.x = acc[i][0] + brow[0]; v0.y = acc[i][1] + brow[1];
        v0.z = acc[i][2] + brow[2]; v0.w = acc[i][3] + brow[3];
        v1.x = acc[i][4] + brow[4]; v1.y = acc[i][5] + brow[5];
        v1.z = acc[i][6] + brow[6]; v1.w = acc[i][7] + brow[7];
        if (RELU) {
            v0.x = fmaxf(v0.x, 0.f); v0.y = fmaxf(v0.y, 0.f);
            v0.z = fmaxf(v0.z, 0.f); v0.w = fmaxf(v0.w, 0.f);
            v1.x = fmaxf(v1.x, 0.f); v1.y = fmaxf(v1.y, 0.f);
            v1.z = fmaxf(v1.z, 0.f); v1.w = fmaxf(v1.w, 0.f);
        }
        *(float4*)(crow)     = v0;
        *(float4*)(crow + 4) = v1;
    }
}

// ---------------------------------------------------------------------------
// Launch: router -> GEMM1(+ReLU) -> GEMM2. All plain launches (graph-safe).
// Output layout (float32): final [B*T*D] | probs [B*E] | expert [B]
// ---------------------------------------------------------------------------
extern "C" void kernel_launch(void* const* d_in, const int* in_sizes, int n_in,
                              void* d_out, int out_size)
{
    const float* x  = (const float*)d_in[0];
    const float* Wp = (const float*)d_in[1];
    const float* bp = (const float*)d_in[2];
    const float* W1 = (const float*)d_in[3];
    const float* b1 = (const float*)d_in[4];
    const float* W2 = (const float*)d_in[5];
    const float* b2 = (const float*)d_in[6];

    float* out        = (float*)d_out;
    float* final_out  = out;
    float* probs_out  = out + (size_t)BB * TT * DD;
    float* expert_out = probs_out + (size_t)BB * EE;

    router_kernel<<<BB, 512>>>(x, Wp, bp, probs_out, expert_out);

    // h[b] = relu(x[b] @ W1[e_b] + b1[e_b])   : M=512, N=2048, K=512
    dim3 g1(HH / 128, TT / 128, BB);           // (16, 4, 32)
    ffn_gemm<HH, DD, true, false, true><<<g1, 256>>>(x, W1, b1, nullptr);

    // out[b] = h[b] @ W2[e_b] + b2[e_b]        : M=512, N=512, K=2048
    dim3 g2(DD / 128, TT / 128, BB);           // (4, 4, 32)
    ffn_gemm<DD, HH, false, true, false><<<g2, 256>>>(nullptr, W2, b2, final_out);
}

// round 3
// speedup vs baseline: 2.6737x; 2.6737x over previous
#include <cuda_runtime.h>
#include <cuda_bf16.h>
#include <math.h>
#include <cstdint>

// Problem constants
#define BB 32
#define TT 512
#define DD 512
#define EE 8
#define HH 2048

// ---------------------------------------------------------------------------
// Device-global scratch (allocation-free)
// ---------------------------------------------------------------------------
__device__ int   g_expert[BB];
__device__ float g_pool_part[BB][8][DD];
__device__ __nv_bfloat16 g_xh[(size_t)BB * TT * DD];
__device__ __nv_bfloat16 g_xl[(size_t)BB * TT * DD];
__device__ __nv_bfloat16 g_w1h[(size_t)EE * HH * DD];   // W1^T : [E][H][D]
__device__ __nv_bfloat16 g_w1l[(size_t)EE * HH * DD];
__device__ __nv_bfloat16 g_w2h[(size_t)EE * DD * HH];   // W2^T : [E][D][H]
__device__ __nv_bfloat16 g_w2l[(size_t)EE * DD * HH];
__device__ __nv_bfloat16 g_hh[(size_t)BB * TT * HH];    // hidden hi
__device__ __nv_bfloat16 g_hl[(size_t)BB * TT * HH];    // hidden lo

// ---------------------------------------------------------------------------
// Baseline-PTX helpers (all sm_80+ features; no sm_103a-only instructions)
// ---------------------------------------------------------------------------
#define SWZ(bo) ((bo) ^ (((bo) >> 3) & 0x70))

#define CP_COMMIT() asm volatile("cp.async.commit_group;" ::: "memory")
#define CP_WAIT(n)  asm volatile("cp.async.wait_group %0;" :: "n"(n) : "memory")

__device__ __forceinline__ uint32_t smem_to_u32(const void* smem_ptr) {
    uint32_t addr;
    asm("{ .reg .u64 tmp; cvta.to.shared.u64 tmp, %1; cvt.u32.u64 %0, tmp; }"
        : "=r"(addr) : "l"(smem_ptr));
    return addr;
}

__device__ __forceinline__ void ldsm4(uint32_t* r, uint32_t addr) {
    asm volatile("ldmatrix.sync.aligned.m8n8.x4.shared.b16 {%0,%1,%2,%3}, [%4];"
                 : "=r"(r[0]), "=r"(r[1]), "=r"(r[2]), "=r"(r[3]) : "r"(addr));
}

__device__ __forceinline__ void mma16816(float* c, const uint32_t* a, const uint32_t* b) {
    asm volatile(
        "mma.sync.aligned.m16n8k16.row.col.f32.bf16.bf16.f32 "
        "{%0,%1,%2,%3}, {%4,%5,%6,%7}, {%8,%9}, {%0,%1,%2,%3};"
        : "+f"(c[0]), "+f"(c[1]), "+f"(c[2]), "+f"(c[3])
        : "r"(a[0]), "r"(a[1]), "r"(a[2]), "r"(a[3]), "r"(b[0]), "r"(b[1]));
}

// cp.async one 128x64(bf16) tile, SW128-swizzled. 4 x 16B per thread (256 thr).
__device__ __forceinline__ void cpa_tile(uint32_t smem_tile,
                                         const __nv_bfloat16* __restrict__ src,
                                         int row0, int k0, int ld, int tid) {
    const char* gbase = (const char*)(src + (size_t)row0 * ld + k0);
    const size_t rs = (size_t)ld * 2;
    #pragma unroll
    for (int j = 0; j < 4; ++j) {
        const int linear = j * 256 + tid;      // 1024 chunks of 16B
        const int row = linear >> 3;
        const int c16 = linear & 7;
        const uint32_t bo = (uint32_t)(row * 128 + c16 * 16);
        const uint32_t dst = smem_tile + SWZ(bo);
        const void* g = gbase + (size_t)row * rs + (size_t)c16 * 16;
        asm volatile("cp.async.cg.shared.global [%0], [%1], 16;"
                     :: "r"(dst), "l"(g) : "memory");
    }
}

// ---------------------------------------------------------------------------
// Router stage 1: partial mean-pool. grid (B, 8), 256 threads, deterministic.
// ---------------------------------------------------------------------------
__global__ void pool_partial_kernel(const float* __restrict__ x) {
    const int b = blockIdx.x, ch = blockIdx.y, tid = threadIdx.x;
    const float2* xb = (const float2*)(x + (size_t)b * TT * DD);
    float2 s = make_float2(0.f, 0.f);
    const int t0 = ch * 64;
    #pragma unroll 4
    for (int t = t0; t < t0 + 64; ++t) {
        float2 v = xb[(size_t)t * 256 + tid];
        s.x += v.x; s.y += v.y;
    }
    g_pool_part[b][ch][tid * 2]     = s.x;
    g_pool_part[b][ch][tid * 2 + 1] = s.y;
}

// ---------------------------------------------------------------------------
// Router stage 2: reduce + logits + softmax + argmax. grid B, 256 threads.
// ---------------------------------------------------------------------------
__global__ void router_final_kernel(const float* __restrict__ Wp,
                                    const float* __restrict__ bp,
                                    float* __restrict__ probs_out,
                                    float* __restrict__ expert_out) {
    const int b = blockIdx.x, tid = threadIdx.x;
    __shared__ float pooled[DD];
    __shared__ float logits[EE];

    for (int d = tid; d < DD; d += 256) {
        float s = 0.f;
        #pragma unroll
        for (int ch = 0; ch < 8; ++ch) s += g_pool_part[b][ch][d];
        pooled[d] = s * (1.0f / (float)TT);
    }
    __syncthreads();

    const int w = tid >> 5, lane = tid & 31;
    if (w < EE) {
        float acc = 0.f;
        for (int d = lane; d < DD; d += 32) acc += pooled[d] * Wp[d * EE + w];
        #pragma unroll
        for (int o = 16; o > 0; o >>= 1) acc += __shfl_down_sync(0xffffffffu, acc, o);
        if (lane == 0) logits[w] = acc + bp[w];
    }
    __syncthreads();

    if (tid == 0) {
        float m = logits[0]; int arg = 0;
        #pragma unroll
        for (int e = 1; e < EE; ++e) if (logits[e] > m) { m = logits[e]; arg = e; }
        float ex[EE], sum = 0.f;
        #pragma unroll
        for (int e = 0; e < EE; ++e) { ex[e] = expf(logits[e] - m); sum += ex[e]; }
        const float inv = 1.0f / sum;
        #pragma unroll
        for (int e = 0; e < EE; ++e) probs_out[b * EE + e] = ex[e] * inv;
        expert_out[b] = (float)arg;
        g_expert[b]   = arg;
    }
}

// ---------------------------------------------------------------------------
// Elementwise split f32 -> (bf16 hi, bf16 lo). Grid-stride over float4s.
// ---------------------------------------------------------------------------
__device__ __forceinline__ void split1(float v, __nv_bfloat16& hi, __nv_bfloat16& lo) {
    hi = __float2bfloat16_rn(v);
    lo = __float2bfloat16_rn(v - __bfloat162float(hi));
}

__global__ void split_x_kernel(const float* __restrict__ x, int n4) {
    const int stride = gridDim.x * blockDim.x;
    for (int i = blockIdx.x * blockDim.x + threadIdx.x; i < n4; i += stride) {
        float4 v = ((const float4*)x)[i];
        __nv_bfloat16 h0, h1, h2, h3, l0, l1, l2, l3;
        split1(v.x, h0, l0); split1(v.y, h1, l1);
        split1(v.z, h2, l2); split1(v.w, h3, l3);
        __nv_bfloat162* ph = (__nv_bfloat162*)g_xh + i * 2;
        __nv_bfloat162* pl = (__nv_bfloat162*)g_xl + i * 2;
        ph[0] = __nv_bfloat162(h0, h1); ph[1] = __nv_bfloat162(h2, h3);
        pl[0] = __nv_bfloat162(l0, l1); pl[1] = __nv_bfloat162(l2, l3);
    }
}

// ---------------------------------------------------------------------------
// Transpose + split: W [E][K][N] f32 -> Wt hi/lo [E][N][K] bf16.
// which=0 -> g_w1h/g_w1l, which=1 -> g_w2h/g_w2l.
// 32x32 tiles, block (32,8). grid (N/32, K/32, E).
// ---------------------------------------------------------------------------
__global__ void split_transpose_kernel(const float* __restrict__ W,
                                       int which, int K, int N) {
    __shared__ float tile[32][33];
    __nv_bfloat16* Th = which ? g_w2h : g_w1h;
    __nv_bfloat16* Tl = which ? g_w2l : g_w1l;

    const int e = blockIdx.z;
    const float* We = W + (size_t)e * K * N;
    __nv_bfloat16* The = Th + (size_t)e * N * K;
    __nv_bfloat16* Tle = Tl + (size_t)e * N * K;
    const int n0 = blockIdx.x * 32, k0 = blockIdx.y * 32;
    const int tx = threadIdx.x, ty = threadIdx.y;

    #pragma unroll
    for (int i = 0; i < 4; ++i) {
        const int k = k0 + ty + i * 8;
        tile[ty + i * 8][tx] = We[(size_t)k * N + n0 + tx];
    }
    __syncthreads();
    #pragma unroll
    for (int i = 0; i < 4; ++i) {
        const int n = n0 + ty + i * 8;
        float v = tile[tx][ty + i * 8];
        __nv_bfloat16 hi, lo; split1(v, hi, lo);
        The[(size_t)n * K + k0 + tx] = hi;
        Tle[(size_t)n * K + k0 + tx] = lo;
    }
}

// ---------------------------------------------------------------------------
// bf16x3 GEMM on mma.sync.m16n8k16 (tensor pipe via HMMA).
//   C[128,128] = A[128,K] @ B[128,K]^T  (B stored [N][K] K-major)
// PHASE 1: A=x(K=512),  B=W1t, epi: bias+relu -> split into g_hh/g_hl
// PHASE 2: A=h(K=2048), B=W2t, epi: bias -> f32 out
// 256 threads = 8 warps (2 M x 4 N), warp tile 64x32.
// SMEM: 2 stages x 4 tiles x 16KB = 128KB, cp.async double-buffered.
// ---------------------------------------------------------------------------
#define STAGE_BYTES 65536
#define GEMM_SMEM_BYTES (2 * STAGE_BYTES)

template<int PHASE>
__global__ void __launch_bounds__(256, 1)
ffn_gemm_mma(const float* __restrict__ bias_all, float* __restrict__ outf)
{
    constexpr int KTOT = (PHASE == 1) ? DD : HH;       // 512 / 2048
    constexpr int NTOT = (PHASE == 1) ? HH : DD;       // 2048 / 512
    constexpr int NCH  = KTOT / 64;

    extern __shared__ char smem[];
    const uint32_t smem_u32 = smem_to_u32(smem);
    const int tid  = threadIdx.x;
    const int wid  = tid >> 5;
    const int lane = tid & 31;

    const int b  = blockIdx.z;
    const int e  = g_expert[b];
    const int m0 = blockIdx.y * 128;
    const int n0 = blockIdx.x * 128;

    const __nv_bfloat16 *Ah, *Al, *Bhp, *Blp;
    if (PHASE == 1) {
        Ah  = g_xh  + (size_t)b * TT * DD;  Al  = g_xl  + (size_t)b * TT * DD;
        Bhp = g_w1h + (size_t)e * HH * DD;  Blp = g_w1l + (size_t)e * HH * DD;
    } else {
        Ah  = g_hh  + (size_t)b * TT * HH;  Al  = g_hl  + (size_t)b * TT * HH;
        Bhp = g_w2h + (size_t)e * DD * HH;  Blp = g_w2l + (size_t)e * DD * HH;
    }
    const float* bias = bias_all + (size_t)e * NTOT;

    const int wm0 = (wid & 1) * 64;       // warp M origin in tile
    const int wn0 = (wid >> 1) * 32;      // warp N origin in tile

    // ldmatrix per-lane address components (swizzle folded in)
    const int aRow = wm0 + (lane & 15);
    const uint32_t aOff  = (uint32_t)aRow * 128u;
    const uint32_t aSw   = ((uint32_t)aRow & 7u) << 4;
    const uint32_t aHalf = ((uint32_t)(lane >> 4)) * 16u;

    const int bRow = wn0 + ((lane >> 4) * 8) + (lane & 7);
    const uint32_t bOff  = (uint32_t)bRow * 128u;
    const uint32_t bSw   = ((uint32_t)bRow & 7u) << 4;
    const uint32_t bHalf = ((uint32_t)((lane >> 3) & 1)) * 16u;

    float acc[4][4][4];
    #pragma unroll
    for (int mi = 0; mi < 4; ++mi)
        #pragma unroll
        for (int ni = 0; ni < 4; ++ni)
            #pragma unroll
            for (int r = 0; r < 4; ++r) acc[mi][ni][r] = 0.f;

    // Prologue: stage 0 <- chunk 0
    {
        const uint32_t st = smem_u32;
        cpa_tile(st,          Ah,  m0, 0, KTOT, tid);
        cpa_tile(st + 16384,  Al,  m0, 0, KTOT, tid);
        cpa_tile(st + 32768,  Bhp, n0, 0, KTOT, tid);
        cpa_tile(st + 49152,  Blp, n0, 0, KTOT, tid);
        CP_COMMIT();
    }

    for (int c = 0; c < NCH; ++c) {
        const int s = c & 1;
        if (c + 1 < NCH) {
            const uint32_t st = smem_u32 + (s ^ 1) * STAGE_BYTES;
            const int k0 = (c + 1) * 64;
            cpa_tile(st,          Ah,  m0, k0, KTOT, tid);
            cpa_tile(st + 16384,  Al,  m0, k0, KTOT, tid);
            cpa_tile(st + 32768,  Bhp, n0, k0, KTOT, tid);
            cpa_tile(st + 49152,  Blp, n0, k0, KTOT, tid);
            CP_COMMIT();
            CP_WAIT(1);
        } else {
            CP_WAIT(0);
        }
        __syncthreads();

        const uint32_t stage = smem_u32 + s * STAGE_BYTES;
        const uint32_t tAh = stage;
        const uint32_t tAl = stage + 16384;
        const uint32_t tBh = stage + 32768;
        const uint32_t tBl = stage + 49152;

        #pragma unroll
        for (int ks = 0; ks < 4; ++ks) {
            const uint32_t colA = ((uint32_t)(ks * 32) + aHalf) ^ aSw;
            const uint32_t colB = ((uint32_t)(ks * 32) + bHalf) ^ bSw;

            uint32_t ah[4][4], al[4][4], bh[4][2], bl[4][2];
            #pragma unroll
            for (int mi = 0; mi < 4; ++mi) {
                ldsm4(ah[mi], tAh + aOff + colA + mi * 2048);
                ldsm4(al[mi], tAl + aOff + colA + mi * 2048);
            }
            #pragma unroll
            for (int j = 0; j < 2; ++j) {
                uint32_t r[4];
                ldsm4(r, tBh + bOff + colB + j * 2048);
                bh[2 * j][0] = r[0]; bh[2 * j][1] = r[1];
                bh[2 * j + 1][0] = r[2]; bh[2 * j + 1][1] = r[3];
                ldsm4(r, tBl + bOff + colB + j * 2048);
                bl[2 * j][0] = r[0]; bl[2 * j][1] = r[1];
                bl[2 * j + 1][0] = r[2]; bl[2 * j + 1][1] = r[3];
            }

            #pragma unroll
            for (int mi = 0; mi < 4; ++mi)
                #pragma unroll
                for (int ni = 0; ni < 4; ++ni)
                    mma16816(acc[mi][ni], ah[mi], bh[ni]);
            #pragma unroll
            for (int mi = 0; mi < 4; ++mi)
                #pragma unroll
                for (int ni = 0; ni < 4; ++ni)
                    mma16816(acc[mi][ni], ah[mi], bl[ni]);
            #pragma unroll
            for (int mi = 0; mi < 4; ++mi)
                #pragma unroll
                for (int ni = 0; ni < 4; ++ni)
                    mma16816(acc[mi][ni], al[mi], bh[ni]);
        }
        __syncthreads();
    }

    // Epilogue. c-frag: c0 (r, col), c1 (r, col+1), c2 (r+8, col), c3 (r+8, col+1)
    const int grow0 = m0 + wm0 + (lane >> 2);
    const int gcol0 = n0 + wn0 + (lane & 3) * 2;

    #pragma unroll
    for (int mi = 0; mi < 4; ++mi) {
        #pragma unroll
        for (int ni = 0; ni < 4; ++ni) {
            const int col = gcol0 + ni * 8;
            const float2 bv = *(const float2*)(bias + col);
            const int r0 = grow0 + mi * 16;
            const int r1 = r0 + 8;

            if (PHASE == 1) {
                float v0 = fmaxf(acc[mi][ni][0] + bv.x, 0.f);
                float v1 = fmaxf(acc[mi][ni][1] + bv.y, 0.f);
                float v2 = fmaxf(acc[mi][ni][2] + bv.x, 0.f);
                float v3 = fmaxf(acc[mi][ni][3] + bv.y, 0.f);
                __nv_bfloat16 h0, h1, h2, h3, l0, l1, l2, l3;
                split1(v0, h0, l0); split1(v1, h1, l1);
                split1(v2, h2, l2); split1(v3, h3, l3);
                const size_t base0 = ((size_t)b * TT + r0) * HH + col;
                const size_t base1 = ((size_t)b * TT + r1) * HH + col;
                *(__nv_bfloat162*)(g_hh + base0) = __nv_bfloat162(h0, h1);
                *(__nv_bfloat162*)(g_hl + base0) = __nv_bfloat162(l0, l1);
                *(__nv_bfloat162*)(g_hh + base1) = __nv_bfloat162(h2, h3);
                *(__nv_bfloat162*)(g_hl + base1) = __nv_bfloat162(l2, l3);
            } else {
                float2 o0, o1;
                o0.x = acc[mi][ni][0] + bv.x; o0.y = acc[mi][ni][1] + bv.y;
                o1.x = acc[mi][ni][2] + bv.x; o1.y = acc[mi][ni][3] + bv.y;
                float* op0 = outf + ((size_t)b * TT + r0) * DD + col;
                float* op1 = outf + ((size_t)b * TT + r1) * DD + col;
                *(float2*)op0 = o0;
                *(float2*)op1 = o1;
            }
        }
    }
}

// ---------------------------------------------------------------------------
// Launch. Output layout (float32): final [B*T*D] | probs [B*E] | expert [B]
// ---------------------------------------------------------------------------
extern "C" void kernel_launch(void* const* d_in, const int* in_sizes, int n_in,
                              void* d_out, int out_size)
{
    const float* x  = (const float*)d_in[0];
    const float* Wp = (const float*)d_in[1];
    const float* bp = (const float*)d_in[2];
    const float* W1 = (const float*)d_in[3];
    const float* b1 = (const float*)d_in[4];
    const float* W2 = (const float*)d_in[5];
    const float* b2 = (const float*)d_in[6];

    float* out        = (float*)d_out;
    float* final_out  = out;
    float* probs_out  = out + (size_t)BB * TT * DD;
    float* expert_out = probs_out + (size_t)BB * EE;

    static bool attr_set = false;
    cudaFuncSetAttribute(ffn_gemm_mma<1>, cudaFuncAttributeMaxDynamicSharedMemorySize,
                         GEMM_SMEM_BYTES);
    cudaFuncSetAttribute(ffn_gemm_mma<2>, cudaFuncAttributeMaxDynamicSharedMemorySize,
                         GEMM_SMEM_BYTES);
    (void)attr_set;

    // Router (deterministic two-stage)
    dim3 gp(BB, 8);
    pool_partial_kernel<<<gp, 256>>>(x);
    router_final_kernel<<<BB, 256>>>(Wp, bp, probs_out, expert_out);

    // Splits
    split_x_kernel<<<592, 256>>>(x, (int)((size_t)BB * TT * DD / 4));
    {
        dim3 gt1(HH / 32, DD / 32, EE);   // W1 [K=512][N=2048] -> [2048][512]
        split_transpose_kernel<<<gt1, dim3(32, 8)>>>(W1, 0, DD, HH);
        dim3 gt2(DD / 32, HH / 32, EE);   // W2 [K=2048][N=512] -> [512][2048]
        split_transpose_kernel<<<gt2, dim3(32, 8)>>>(W2, 1, HH, DD);
    }

    // GEMM1: h = relu(x @ W1[e] + b1[e])   M=512, N=2048, K=512
    dim3 g1(HH / 128, TT / 128, BB);      // (16, 4, 32)
    ffn_gemm_mma<1><<<g1, 256, GEMM_SMEM_BYTES>>>(b1, nullptr);

    // GEMM2: out = h @ W2[e] + b2[e]       M=512, N=512, K=2048
    dim3 g2(DD / 128, TT / 128, BB);      // (4, 4, 32)
    ffn_gemm_mma<2><<<g2, 256, GEMM_SMEM_BYTES>>>(b2, final_out);
}

// round 6
// speedup vs baseline: 4.0009x; 1.4964x over previous
#include <cuda_runtime.h>
#include <cuda_fp16.h>
#include <math.h>
#include <cstdint>

// Problem constants
#define BB 32
#define TT 512
#define DD 512
#define EE 8
#define HH 2048

// ---------------------------------------------------------------------------
// Device-global scratch (allocation-free)
// ---------------------------------------------------------------------------
__device__ int   g_expert[BB];
__device__ float g_pool_part[BB][8][DD];
__device__ __half g_x16[(size_t)BB * TT * DD];          // x as fp16
__device__ __half g_w1h[(size_t)EE * HH * DD];          // W1^T hi : [E][H][D]
__device__ __half g_w1l[(size_t)EE * HH * DD];          // W1^T lo
__device__ __half g_w2h[(size_t)EE * DD * HH];          // W2^T hi : [E][D][H]
__device__ __half g_w2l[(size_t)EE * DD * HH];          // W2^T lo
__device__ __half g_h16[(size_t)BB * TT * HH];          // hidden as fp16

// ---------------------------------------------------------------------------
// Baseline-PTX helpers (sm_80-level features only; compiles at .target sm_103)
// ---------------------------------------------------------------------------
#define SWZ(bo) ((bo) ^ (((bo) >> 3) & 0x70))

#define CP_COMMIT() asm volatile("cp.async.commit_group;" ::: "memory")
#define CP_WAIT(n)  asm volatile("cp.async.wait_group %0;" :: "n"(n) : "memory")

__device__ __forceinline__ uint32_t smem_to_u32(const void* smem_ptr) {
    uint32_t addr;
    asm("{ .reg .u64 tmp; cvta.to.shared.u64 tmp, %1; cvt.u32.u64 %0, tmp; }"
        : "=r"(addr) : "l"(smem_ptr));
    return addr;
}

__device__ __forceinline__ void ldsm4(uint32_t* r, uint32_t addr) {
    asm volatile("ldmatrix.sync.aligned.m8n8.x4.shared.b16 {%0,%1,%2,%3}, [%4];"
                 : "=r"(r[0]), "=r"(r[1]), "=r"(r[2]), "=r"(r[3]) : "r"(addr));
}

__device__ __forceinline__ void mma16816(float* c, const uint32_t* a, const uint32_t* b) {
    asm volatile(
        "mma.sync.aligned.m16n8k16.row.col.f32.f16.f16.f32 "
        "{%0,%1,%2,%3}, {%4,%5,%6,%7}, {%8,%9}, {%0,%1,%2,%3};"
        : "+f"(c[0]), "+f"(c[1]), "+f"(c[2]), "+f"(c[3])
        : "r"(a[0]), "r"(a[1]), "r"(a[2]), "r"(a[3]), "r"(b[0]), "r"(b[1]));
}

// cp.async one ROWSx64(fp16) tile (128B rows, SW128-swizzled). 256 threads.
template<int ROWS>
__device__ __forceinline__ void cpa_tile(uint32_t smem_tile,
                                         const __half* __restrict__ src,
                                         int row0, int k0, int ld, int tid) {
    const char* gbase = (const char*)(src + (size_t)row0 * ld + k0);
    const size_t rs = (size_t)ld * 2;
    #pragma unroll
    for (int j = 0; j < ROWS / 32; ++j) {
        const int linear = j * 256 + tid;      // ROWS*8 chunks of 16B
        const int row = linear >> 3;
        const int c16 = linear & 7;
        const uint32_t bo = (uint32_t)(row * 128 + c16 * 16);
        const uint32_t dst = smem_tile + SWZ(bo);
        const void* g = gbase + (size_t)row * rs + (size_t)c16 * 16;
        asm volatile("cp.async.cg.shared.global [%0], [%1], 16;"
                     :: "r"(dst), "l"(g) : "memory");
    }
}

// ---------------------------------------------------------------------------
// Router stage 1 (fused): partial mean-pool AND x -> fp16 conversion.
// grid (B, 8), 256 threads; each element of x read exactly once.
// ---------------------------------------------------------------------------
__global__ void pool_split_kernel(const float* __restrict__ x) {
    const int b = blockIdx.x, ch = blockIdx.y, tid = threadIdx.x;
    const float2* xb = (const float2*)(x + (size_t)b * TT * DD);
    __half2* xo = (__half2*)(g_x16 + (size_t)b * TT * DD);
    float2 s = make_float2(0.f, 0.f);
    const int t0 = ch * 64;
    #pragma unroll 4
    for (int t = t0; t < t0 + 64; ++t) {
        float2 v = xb[(size_t)t * 256 + tid];
        s.x += v.x; s.y += v.y;
        xo[(size_t)t * 256 + tid] = __floats2half2_rn(v.x, v.y);
    }
    g_pool_part[b][ch][tid * 2]     = s.x;
    g_pool_part[b][ch][tid * 2 + 1] = s.y;
}

// ---------------------------------------------------------------------------
// Router stage 2: reduce + logits + softmax + argmax. grid B, 256 threads.
// ---------------------------------------------------------------------------
__global__ void router_final_kernel(const float* __restrict__ Wp,
                                    const float* __restrict__ bp,
                                    float* __restrict__ probs_out,
                                    float* __restrict__ expert_out) {
    const int b = blockIdx.x, tid = threadIdx.x;
    __shared__ float pooled[DD];
    __shared__ float logits[EE];

    for (int d = tid; d < DD; d += 256) {
        float s = 0.f;
        #pragma unroll
        for (int ch = 0; ch < 8; ++ch) s += g_pool_part[b][ch][d];
        pooled[d] = s * (1.0f / (float)TT);
    }
    __syncthreads();

    const int w = tid >> 5, lane = tid & 31;
    if (w < EE) {
        float acc = 0.f;
        for (int d = lane; d < DD; d += 32) acc += pooled[d] * Wp[d * EE + w];
        #pragma unroll
        for (int o = 16; o > 0; o >>= 1) acc += __shfl_down_sync(0xffffffffu, acc, o);
        if (lane == 0) logits[w] = acc + bp[w];
    }
    __syncthreads();

    if (tid == 0) {
        float m = logits[0]; int arg = 0;
        #pragma unroll
        for (int e = 1; e < EE; ++e) if (logits[e] > m) { m = logits[e]; arg = e; }
        float ex[EE], sum = 0.f;
        #pragma unroll
        for (int e = 0; e < EE; ++e) { ex[e] = expf(logits[e] - m); sum += ex[e]; }
        const float inv = 1.0f / sum;
        #pragma unroll
        for (int e = 0; e < EE; ++e) probs_out[b * EE + e] = ex[e] * inv;
        expert_out[b] = (float)arg;
        g_expert[b]   = arg;
    }
}

// ---------------------------------------------------------------------------
// fp16 hi/lo split
// ---------------------------------------------------------------------------
__device__ __forceinline__ void split1h(float v, __half& hi, __half& lo) {
    hi = __float2half_rn(v);
    lo = __float2half_rn(v - __half2float(hi));
}

// ---------------------------------------------------------------------------
// Transpose + split: W [E][K][N] f32 -> Wt hi/lo [E][N][K] fp16.
// which=0 -> g_w1h/g_w1l, which=1 -> g_w2h/g_w2l.
// 32x32 tiles, block (32,8). grid (N/32, K/32, E).
// ---------------------------------------------------------------------------
__global__ void split_transpose_kernel(const float* __restrict__ W,
                                       int which, int K, int N) {
    __shared__ float tile[32][33];
    __half* Th = which ? g_w2h : g_w1h;
    __half* Tl = which ? g_w2l : g_w1l;

    const int e = blockIdx.z;
    const float* We = W + (size_t)e * K * N;
    __half* The = Th + (size_t)e * N * K;
    __half* Tle = Tl + (size_t)e * N * K;
    const int n0 = blockIdx.x * 32, k0 = blockIdx.y * 32;
    const int tx = threadIdx.x, ty = threadIdx.y;

    #pragma unroll
    for (int i = 0; i < 4; ++i) {
        const int k = k0 + ty + i * 8;
        tile[ty + i * 8][tx] = We[(size_t)k * N + n0 + tx];
    }
    __syncthreads();
    #pragma unroll
    for (int i = 0; i < 4; ++i) {
        const int n = n0 + ty + i * 8;
        float v = tile[tx][ty + i * 8];
        __half hi, lo; split1h(v, hi, lo);
        The[(size_t)n * K + k0 + tx] = hi;
        Tle[(size_t)n * K + k0 + tx] = lo;
    }
}

// ---------------------------------------------------------------------------
// fp16 2-term GEMM on mma.sync.m16n8k16:
//   C[128,256] = A[128,K] @ (Bh + Bl)[256,K]^T   (B stored [N][K] K-major)
// PHASE 1: A=x16(K=512),  B=W1t, epi: bias+relu -> fp16 -> g_h16
// PHASE 2: A=h16(K=2048), B=W2t, epi: bias -> f32 out
// 256 threads = 8 warps (2 M x 4 N), warp tile 64x64, acc 128 regs/thread.
// SMEM/stage: A 16KB + Bh 32KB + Bl 32KB = 80KB; 2 stages = 160KB.
// ---------------------------------------------------------------------------
#define STAGE_BYTES 81920
#define A_OFF  0
#define BH_OFF 16384
#define BL_OFF 49152
#define GEMM_SMEM_BYTES (2 * STAGE_BYTES)

template<int PHASE>
__global__ void __launch_bounds__(256, 1)
ffn_gemm_mma(const float* __restrict__ bias_all, float* __restrict__ outf)
{
    constexpr int KTOT = (PHASE == 1) ? DD : HH;       // 512 / 2048
    constexpr int NTOT = (PHASE == 1) ? HH : DD;       // 2048 / 512
    constexpr int NCH  = KTOT / 64;

    extern __shared__ char smem[];
    const uint32_t smem_u32 = smem_to_u32(smem);
    const int tid  = threadIdx.x;
    const int wid  = tid >> 5;
    const int lane = tid & 31;

    const int b  = blockIdx.z;
    const int e  = g_expert[b];
    const int m0 = blockIdx.y * 128;
    const int n0 = blockIdx.x * 256;

    const __half *A16, *Bhp, *Blp;
    if (PHASE == 1) {
        A16 = g_x16 + (size_t)b * TT * DD;
        Bhp = g_w1h + (size_t)e * HH * DD;  Blp = g_w1l + (size_t)e * HH * DD;
    } else {
        A16 = g_h16 + (size_t)b * TT * HH;
        Bhp = g_w2h + (size_t)e * DD * HH;  Blp = g_w2l + (size_t)e * DD * HH;
    }
    const float* bias = bias_all + (size_t)e * NTOT;

    const int wm0 = (wid & 1) * 64;       // warp M origin in tile
    const int wn0 = (wid >> 1) * 64;      // warp N origin in tile

    // ldmatrix per-lane address components (SW128 swizzle folded in)
    const int aRow = wm0 + (lane & 15);
    const uint32_t aOff  = (uint32_t)aRow * 128u;
    const uint32_t aSw   = ((uint32_t)aRow & 7u) << 4;
    const uint32_t aHalf = ((uint32_t)(lane >> 4)) * 16u;

    const int bRow = wn0 + ((lane >> 4) * 8) + (lane & 7);
    const uint32_t bOff  = (uint32_t)bRow * 128u;
    const uint32_t bSw   = ((uint32_t)bRow & 7u) << 4;
    const uint32_t bHalf = ((uint32_t)((lane >> 3) & 1)) * 16u;

    float acc[4][8][4];
    #pragma unroll
    for (int mi = 0; mi < 4; ++mi)
        #pragma unroll
        for (int ni = 0; ni < 8; ++ni)
            #pragma unroll
            for (int r = 0; r < 4; ++r) acc[mi][ni][r] = 0.f;

    // Prologue: stage 0 <- chunk 0
    cpa_tile<128>(smem_u32 + A_OFF,  A16, m0, 0, KTOT, tid);
    cpa_tile<256>(smem_u32 + BH_OFF, Bhp, n0, 0, KTOT, tid);
    cpa_tile<256>(smem_u32 + BL_OFF, Blp, n0, 0, KTOT, tid);
    CP_COMMIT();

    for (int c = 0; c < NCH; ++c) {
        const int s = c & 1;
        if (c + 1 < NCH) {
            const uint32_t st = smem_u32 + (s ^ 1) * STAGE_BYTES;
            const int k0 = (c + 1) * 64;
            cpa_tile<128>(st + A_OFF,  A16, m0, k0, KTOT, tid);
            cpa_tile<256>(st + BH_OFF, Bhp, n0, k0, KTOT, tid);
            cpa_tile<256>(st + BL_OFF, Blp, n0, k0, KTOT, tid);
            CP_COMMIT();
            CP_WAIT(1);
        } else {
            CP_WAIT(0);
        }
        __syncthreads();

        const uint32_t stage = smem_u32 + s * STAGE_BYTES;
        const uint32_t tA  = stage + A_OFF;
        const uint32_t tBh = stage + BH_OFF;
        const uint32_t tBl = stage + BL_OFF;

        #pragma unroll
        for (int ks = 0; ks < 4; ++ks) {
            const uint32_t colA = ((uint32_t)(ks * 32) + aHalf) ^ aSw;
            const uint32_t colB = ((uint32_t)(ks * 32) + bHalf) ^ bSw;

            uint32_t a[4][4];
            #pragma unroll
            for (int mi = 0; mi < 4; ++mi)
                ldsm4(a[mi], tA + aOff + colA + mi * 2048);

            // hi pass
            {
                uint32_t bh[8][2];
                #pragma unroll
                for (int j = 0; j < 4; ++j) {
                    uint32_t r[4];
                    ldsm4(r, tBh + bOff + colB + j * 2048);
                    bh[2 * j][0] = r[0]; bh[2 * j][1] = r[1];
                    bh[2 * j + 1][0] = r[2]; bh[2 * j + 1][1] = r[3];
                }
                #pragma unroll
                for (int mi = 0; mi < 4; ++mi)
                    #pragma unroll
                    for (int ni = 0; ni < 8; ++ni)
                        mma16816(acc[mi][ni], a[mi], bh[ni]);
            }
            // lo pass
            {
                uint32_t bl[8][2];
                #pragma unroll
                for (int j = 0; j < 4; ++j) {
                    uint32_t r[4];
                    ldsm4(r, tBl + bOff + colB + j * 2048);
                    bl[2 * j][0] = r[0]; bl[2 * j][1] = r[1];
                    bl[2 * j + 1][0] = r[2]; bl[2 * j + 1][1] = r[3];
                }
                #pragma unroll
                for (int mi = 0; mi < 4; ++mi)
                    #pragma unroll
                    for (int ni = 0; ni < 8; ++ni)
                        mma16816(acc[mi][ni], a[mi], bl[ni]);
            }
        }
        __syncthreads();
    }

    // Epilogue. c-frag: c0 (r, col), c1 (r, col+1), c2 (r+8, col), c3 (r+8, col+1)
    const int grow0 = m0 + wm0 + (lane >> 2);
    const int gcol0 = n0 + wn0 + (lane & 3) * 2;

    #pragma unroll
    for (int mi = 0; mi < 4; ++mi) {
        #pragma unroll
        for (int ni = 0; ni < 8; ++ni) {
            const int col = gcol0 + ni * 8;
            const float2 bv = *(const float2*)(bias + col);
            const int r0 = grow0 + mi * 16;
            const int r1 = r0 + 8;

            if (PHASE == 1) {
                float v0 = fmaxf(acc[mi][ni][0] + bv.x, 0.f);
                float v1 = fmaxf(acc[mi][ni][1] + bv.y, 0.f);
                float v2 = fmaxf(acc[mi][ni][2] + bv.x, 0.f);
                float v3 = fmaxf(acc[mi][ni][3] + bv.y, 0.f);
                const size_t base0 = ((size_t)b * TT + r0) * HH + col;
                const size_t base1 = ((size_t)b * TT + r1) * HH + col;
                *(__half2*)(g_h16 + base0) = __floats2half2_rn(v0, v1);
                *(__half2*)(g_h16 + base1) = __floats2half2_rn(v2, v3);
            } else {
                float2 o0, o1;
                o0.x = acc[mi][ni][0] + bv.x; o0.y = acc[mi][ni][1] + bv.y;
                o1.x = acc[mi][ni][2] + bv.x; o1.y = acc[mi][ni][3] + bv.y;
                float* op0 = outf + ((size_t)b * TT + r0) * DD + col;
                float* op1 = outf + ((size_t)b * TT + r1) * DD + col;
                *(float2*)op0 = o0;
                *(float2*)op1 = o1;
            }
        }
    }
}

// ---------------------------------------------------------------------------
// Launch. Output layout (float32): final [B*T*D] | probs [B*E] | expert [B]
// ---------------------------------------------------------------------------
extern "C" void kernel_launch(void* const* d_in, const int* in_sizes, int n_in,
                              void* d_out, int out_size)
{
    const float* x  = (const float*)d_in[0];
    const float* Wp = (const float*)d_in[1];
    const float* bp = (const float*)d_in[2];
    const float* W1 = (const float*)d_in[3];
    const float* b1 = (const float*)d_in[4];
    const float* W2 = (const float*)d_in[5];
    const float* b2 = (const float*)d_in[6];

    float* out        = (float*)d_out;
    float* final_out  = out;
    float* probs_out  = out + (size_t)BB * TT * DD;
    float* expert_out = probs_out + (size_t)BB * EE;

    cudaFuncSetAttribute(ffn_gemm_mma<1>, cudaFuncAttributeMaxDynamicSharedMemorySize,
                         GEMM_SMEM_BYTES);
    cudaFuncSetAttribute(ffn_gemm_mma<2>, cudaFuncAttributeMaxDynamicSharedMemorySize,
                         GEMM_SMEM_BYTES);

    // Router + fused x->fp16 conversion
    dim3 gp(BB, 8);
    pool_split_kernel<<<gp, 256>>>(x);
    router_final_kernel<<<BB, 256>>>(Wp, bp, probs_out, expert_out);

    // Weight transpose + fp16 hi/lo split
    {
        dim3 gt1(HH / 32, DD / 32, EE);   // W1 [K=512][N=2048] -> [2048][512]
        split_transpose_kernel<<<gt1, dim3(32, 8)>>>(W1, 0, DD, HH);
        dim3 gt2(DD / 32, HH / 32, EE);   // W2 [K=2048][N=512] -> [512][2048]
        split_transpose_kernel<<<gt2, dim3(32, 8)>>>(W2, 1, HH, DD);
    }

    // GEMM1: h = relu(x @ W1[e] + b1[e])   M=512, N=2048, K=512
    dim3 g1(HH / 256, TT / 128, BB);      // (8, 4, 32)
    ffn_gemm_mma<1><<<g1, 256, GEMM_SMEM_BYTES>>>(b1, nullptr);

    // GEMM2: out = h @ W2[e] + b2[e]       M=512, N=512, K=2048
    dim3 g2(DD / 256, TT / 128, BB);      // (2, 4, 32)
    ffn_gemm_mma<2><<<g2, 256, GEMM_SMEM_BYTES>>>(b2, final_out);
}

// round 7
// speedup vs baseline: 6.1855x; 1.5460x over previous
#include <cuda_runtime.h>
#include <cuda_fp16.h>
#include <math.h>
#include <cstdint>

// Problem constants
#define BB 32
#define TT 512
#define DD 512
#define EE 8
#define HH 2048

// ---------------------------------------------------------------------------
// Device-global scratch (allocation-free)
// ---------------------------------------------------------------------------
__device__ int   g_expert[BB];
__device__ float g_pool_part[BB][8][DD];
__device__ __half g_x16[(size_t)BB * TT * DD];          // x as fp16
__device__ __half g_w1t[(size_t)EE * HH * DD];          // W1^T : [E][H][D] fp16
__device__ __half g_w2t[(size_t)EE * DD * HH];          // W2^T : [E][D][H] fp16
__device__ __half g_h16[(size_t)BB * TT * HH];          // hidden as fp16

// ---------------------------------------------------------------------------
// Baseline-PTX helpers (sm_80-level features only; compiles at .target sm_103)
// ---------------------------------------------------------------------------
#define SWZ(bo) ((bo) ^ (((bo) >> 3) & 0x70))

#define CP_COMMIT() asm volatile("cp.async.commit_group;" ::: "memory")
#define CP_WAIT(n)  asm volatile("cp.async.wait_group %0;" :: "n"(n) : "memory")

__device__ __forceinline__ uint32_t smem_to_u32(const void* smem_ptr) {
    uint32_t addr;
    asm("{ .reg .u64 tmp; cvta.to.shared.u64 tmp, %1; cvt.u32.u64 %0, tmp; }"
        : "=r"(addr) : "l"(smem_ptr));
    return addr;
}

__device__ __forceinline__ void ldsm4(uint32_t* r, uint32_t addr) {
    asm volatile("ldmatrix.sync.aligned.m8n8.x4.shared.b16 {%0,%1,%2,%3}, [%4];"
                 : "=r"(r[0]), "=r"(r[1]), "=r"(r[2]), "=r"(r[3]) : "r"(addr));
}

__device__ __forceinline__ void mma16816(float* c, const uint32_t* a, const uint32_t* b) {
    asm volatile(
        "mma.sync.aligned.m16n8k16.row.col.f32.f16.f16.f32 "
        "{%0,%1,%2,%3}, {%4,%5,%6,%7}, {%8,%9}, {%0,%1,%2,%3};"
        : "+f"(c[0]), "+f"(c[1]), "+f"(c[2]), "+f"(c[3])
        : "r"(a[0]), "r"(a[1]), "r"(a[2]), "r"(a[3]), "r"(b[0]), "r"(b[1]));
}

// cp.async one ROWSx64(fp16) tile (128B rows, SW128-swizzled). 256 threads.
template<int ROWS>
__device__ __forceinline__ void cpa_tile(uint32_t smem_tile,
                                         const __half* __restrict__ src,
                                         int row0, int k0, int ld, int tid) {
    const char* gbase = (const char*)(src + (size_t)row0 * ld + k0);
    const size_t rs = (size_t)ld * 2;
    #pragma unroll
    for (int j = 0; j < ROWS / 32; ++j) {
        const int linear = j * 256 + tid;      // ROWS*8 chunks of 16B
        const int row = linear >> 3;
        const int c16 = linear & 7;
        const uint32_t bo = (uint32_t)(row * 128 + c16 * 16);
        const uint32_t dst = smem_tile + SWZ(bo);
        const void* g = gbase + (size_t)row * rs + (size_t)c16 * 16;
        asm volatile("cp.async.cg.shared.global [%0], [%1], 16;"
                     :: "r"(dst), "l"(g) : "memory");
    }
}

// ---------------------------------------------------------------------------
// Router stage 1 (fused): partial mean-pool AND x -> fp16 conversion.
// grid (B, 8), 256 threads; each element of x read exactly once.
// ---------------------------------------------------------------------------
__global__ void pool_split_kernel(const float* __restrict__ x) {
    const int b = blockIdx.x, ch = blockIdx.y, tid = threadIdx.x;
    const float2* xb = (const float2*)(x + (size_t)b * TT * DD);
    __half2* xo = (__half2*)(g_x16 + (size_t)b * TT * DD);
    float2 s = make_float2(0.f, 0.f);
    const int t0 = ch * 64;
    #pragma unroll 4
    for (int t = t0; t < t0 + 64; ++t) {
        float2 v = xb[(size_t)t * 256 + tid];
        s.x += v.x; s.y += v.y;
        xo[(size_t)t * 256 + tid] = __floats2half2_rn(v.x, v.y);
    }
    g_pool_part[b][ch][tid * 2]     = s.x;
    g_pool_part[b][ch][tid * 2 + 1] = s.y;
}

// ---------------------------------------------------------------------------
// Router stage 2: reduce + logits + softmax + argmax. grid B, 256 threads.
// ---------------------------------------------------------------------------
__global__ void router_final_kernel(const float* __restrict__ Wp,
                                    const float* __restrict__ bp,
                                    float* __restrict__ probs_out,
                                    float* __restrict__ expert_out) {
    const int b = blockIdx.x, tid = threadIdx.x;
    __shared__ float pooled[DD];
    __shared__ float logits[EE];

    for (int d = tid; d < DD; d += 256) {
        float s = 0.f;
        #pragma unroll
        for (int ch = 0; ch < 8; ++ch) s += g_pool_part[b][ch][d];
        pooled[d] = s * (1.0f / (float)TT);
    }
    __syncthreads();

    const int w = tid >> 5, lane = tid & 31;
    if (w < EE) {
        float acc = 0.f;
        for (int d = lane; d < DD; d += 32) acc += pooled[d] * Wp[d * EE + w];
        #pragma unroll
        for (int o = 16; o > 0; o >>= 1) acc += __shfl_down_sync(0xffffffffu, acc, o);
        if (lane == 0) logits[w] = acc + bp[w];
    }
    __syncthreads();

    if (tid == 0) {
        float m = logits[0]; int arg = 0;
        #pragma unroll
        for (int e = 1; e < EE; ++e) if (logits[e] > m) { m = logits[e]; arg = e; }
        float ex[EE], sum = 0.f;
        #pragma unroll
        for (int e = 0; e < EE; ++e) { ex[e] = expf(logits[e] - m); sum += ex[e]; }
        const float inv = 1.0f / sum;
        #pragma unroll
        for (int e = 0; e < EE; ++e) probs_out[b * EE + e] = ex[e] * inv;
        expert_out[b] = (float)arg;
        g_expert[b]   = arg;
    }
}

// ---------------------------------------------------------------------------
// Transpose + convert: W [E][K][N] f32 -> Wt [E][N][K] fp16.
// which=0 -> g_w1t, which=1 -> g_w2t.
// 32x32 tiles, block (32,8). grid (N/32, K/32, E).
// ---------------------------------------------------------------------------
__global__ void transpose_cvt_kernel(const float* __restrict__ W,
                                     int which, int K, int N) {
    __shared__ float tile[32][33];
    __half* Th = which ? g_w2t : g_w1t;

    const int e = blockIdx.z;
    const float* We = W + (size_t)e * K * N;
    __half* The = Th + (size_t)e * N * K;
    const int n0 = blockIdx.x * 32, k0 = blockIdx.y * 32;
    const int tx = threadIdx.x, ty = threadIdx.y;

    #pragma unroll
    for (int i = 0; i < 4; ++i) {
        const int k = k0 + ty + i * 8;
        tile[ty + i * 8][tx] = We[(size_t)k * N + n0 + tx];
    }
    __syncthreads();
    #pragma unroll
    for (int i = 0; i < 4; ++i) {
        const int n = n0 + ty + i * 8;
        The[(size_t)n * K + k0 + tx] = __float2half_rn(tile[tx][ty + i * 8]);
    }
}

// ---------------------------------------------------------------------------
// fp16 GEMM on mma.sync.m16n8k16:
//   C[256,128] = A[256,K] @ B[128,K]^T   (B stored [N][K] K-major)
// PHASE 1: A=x16(K=512),  B=W1t, epi: bias+relu -> fp16 -> g_h16
// PHASE 2: A=h16(K=2048), B=W2t, epi: bias -> f32 out
// 256 threads = 8 warps (4 M x 2 N), warp tile 64x64, acc 128 regs/thread.
// SMEM/stage: A 32KB + B 16KB = 48KB; 3 stages = 144KB, cp.async ring.
// ---------------------------------------------------------------------------
#define STAGE_BYTES 49152
#define A_OFF  0
#define B_OFF  32768
#define GEMM_SMEM_BYTES (3 * STAGE_BYTES)

template<int PHASE>
__global__ void __launch_bounds__(256, 1)
ffn_gemm_mma(const float* __restrict__ bias_all, float* __restrict__ outf)
{
    constexpr int KTOT = (PHASE == 1) ? DD : HH;       // 512 / 2048
    constexpr int NTOT = (PHASE == 1) ? HH : DD;       // 2048 / 512
    constexpr int NCH  = KTOT / 64;                    // 8 / 32

    extern __shared__ char smem[];
    const uint32_t smem_u32 = smem_to_u32(smem);
    const int tid  = threadIdx.x;
    const int wid  = tid >> 5;
    const int lane = tid & 31;

    const int b  = blockIdx.z;
    const int e  = g_expert[b];
    const int m0 = blockIdx.y * 256;
    const int n0 = blockIdx.x * 128;

    const __half *A16, *Bp;
    if (PHASE == 1) {
        A16 = g_x16 + (size_t)b * TT * DD;
        Bp  = g_w1t + (size_t)e * HH * DD;
    } else {
        A16 = g_h16 + (size_t)b * TT * HH;
        Bp  = g_w2t + (size_t)e * DD * HH;
    }
    const float* bias = bias_all + (size_t)e * NTOT;

    const int wm0 = (wid & 3) * 64;       // warp M origin in CTA tile (4 tiles)
    const int wn0 = (wid >> 2) * 64;      // warp N origin in CTA tile (2 tiles)

    // ldmatrix per-lane address components (SW128 swizzle folded in)
    const int aRow = wm0 + (lane & 15);
    const uint32_t aOff  = (uint32_t)aRow * 128u;
    const uint32_t aSw   = ((uint32_t)aRow & 7u) << 4;
    const uint32_t aHalf = ((uint32_t)(lane >> 4)) * 16u;

    const int bRow = wn0 + ((lane >> 4) * 8) + (lane & 7);
    const uint32_t bOff  = (uint32_t)bRow * 128u;
    const uint32_t bSw   = ((uint32_t)bRow & 7u) << 4;
    const uint32_t bHalf = ((uint32_t)((lane >> 3) & 1)) * 16u;

    float acc[4][8][4];
    #pragma unroll
    for (int mi = 0; mi < 4; ++mi)
        #pragma unroll
        for (int ni = 0; ni < 8; ++ni)
            #pragma unroll
            for (int r = 0; r < 4; ++r) acc[mi][ni][r] = 0.f;

    // Prologue: load chunks 0 and 1 into ring slots 0, 1
    cpa_tile<256>(smem_u32 + 0 * STAGE_BYTES + A_OFF, A16, m0, 0, KTOT, tid);
    cpa_tile<128>(smem_u32 + 0 * STAGE_BYTES + B_OFF, Bp,  n0, 0, KTOT, tid);
    CP_COMMIT();
    cpa_tile<256>(smem_u32 + 1 * STAGE_BYTES + A_OFF, A16, m0, 64, KTOT, tid);
    cpa_tile<128>(smem_u32 + 1 * STAGE_BYTES + B_OFF, Bp,  n0, 64, KTOT, tid);
    CP_COMMIT();

    int slot = 0;
    #pragma unroll 2
    for (int c = 0; c < NCH; ++c) {
        if (c + 2 < NCH) {
            const int ps = (slot + 2 >= 3) ? slot - 1 : slot + 2;  // (c+2)%3
            const uint32_t st = smem_u32 + ps * STAGE_BYTES;
            const int k0 = (c + 2) * 64;
            cpa_tile<256>(st + A_OFF, A16, m0, k0, KTOT, tid);
            cpa_tile<128>(st + B_OFF, Bp,  n0, k0, KTOT, tid);
            CP_COMMIT();
            CP_WAIT(2);
        } else if (c + 1 < NCH) {
            CP_WAIT(1);
        } else {
            CP_WAIT(0);
        }
        __syncthreads();

        const uint32_t stage = smem_u32 + slot * STAGE_BYTES;
        const uint32_t tA = stage + A_OFF;
        const uint32_t tB = stage + B_OFF;

        #pragma unroll
        for (int ks = 0; ks < 4; ++ks) {
            const uint32_t colA = ((uint32_t)(ks * 32) + aHalf) ^ aSw;
            const uint32_t colB = ((uint32_t)(ks * 32) + bHalf) ^ bSw;

            uint32_t a[4][4];
            #pragma unroll
            for (int mi = 0; mi < 4; ++mi)
                ldsm4(a[mi], tA + aOff + colA + mi * 2048);

            uint32_t bfrag[8][2];
            #pragma unroll
            for (int j = 0; j < 4; ++j) {
                uint32_t r[4];
                ldsm4(r, tB + bOff + colB + j * 2048);
                bfrag[2 * j][0] = r[0]; bfrag[2 * j][1] = r[1];
                bfrag[2 * j + 1][0] = r[2]; bfrag[2 * j + 1][1] = r[3];
            }

            #pragma unroll
            for (int mi = 0; mi < 4; ++mi)
                #pragma unroll
                for (int ni = 0; ni < 8; ++ni)
                    mma16816(acc[mi][ni], a[mi], bfrag[ni]);
        }
        __syncthreads();

        slot = (slot + 1 >= 3) ? 0 : slot + 1;
    }

    // Epilogue. c-frag: c0 (r, col), c1 (r, col+1), c2 (r+8, col), c3 (r+8, col+1)
    const int grow0 = m0 + wm0 + (lane >> 2);
    const int gcol0 = n0 + wn0 + (lane & 3) * 2;

    #pragma unroll
    for (int mi = 0; mi < 4; ++mi) {
        #pragma unroll
        for (int ni = 0; ni < 8; ++ni) {
            const int col = gcol0 + ni * 8;
            const float2 bv = *(const float2*)(bias + col);
            const int r0 = grow0 + mi * 16;
            const int r1 = r0 + 8;

            if (PHASE == 1) {
                float v0 = fmaxf(acc[mi][ni][0] + bv.x, 0.f);
                float v1 = fmaxf(acc[mi][ni][1] + bv.y, 0.f);
                float v2 = fmaxf(acc[mi][ni][2] + bv.x, 0.f);
                float v3 = fmaxf(acc[mi][ni][3] + bv.y, 0.f);
                const size_t base0 = ((size_t)b * TT + r0) * HH + col;
                const size_t base1 = ((size_t)b * TT + r1) * HH + col;
                *(__half2*)(g_h16 + base0) = __floats2half2_rn(v0, v1);
                *(__half2*)(g_h16 + base1) = __floats2half2_rn(v2, v3);
            } else {
                float2 o0, o1;
                o0.x = acc[mi][ni][0] + bv.x; o0.y = acc[mi][ni][1] + bv.y;
                o1.x = acc[mi][ni][2] + bv.x; o1.y = acc[mi][ni][3] + bv.y;
                float* op0 = outf + ((size_t)b * TT + r0) * DD + col;
                float* op1 = outf + ((size_t)b * TT + r1) * DD + col;
                *(float2*)op0 = o0;
                *(float2*)op1 = o1;
            }
        }
    }
}

// ---------------------------------------------------------------------------
// Launch. Output layout (float32): final [B*T*D] | probs [B*E] | expert [B]
// ---------------------------------------------------------------------------
extern "C" void kernel_launch(void* const* d_in, const int* in_sizes, int n_in,
                              void* d_out, int out_size)
{
    const float* x  = (const float*)d_in[0];
    const float* Wp = (const float*)d_in[1];
    const float* bp = (const float*)d_in[2];
    const float* W1 = (const float*)d_in[3];
    const float* b1 = (const float*)d_in[4];
    const float* W2 = (const float*)d_in[5];
    const float* b2 = (const float*)d_in[6];

    float* out        = (float*)d_out;
    float* final_out  = out;
    float* probs_out  = out + (size_t)BB * TT * DD;
    float* expert_out = probs_out + (size_t)BB * EE;

    cudaFuncSetAttribute(ffn_gemm_mma<1>, cudaFuncAttributeMaxDynamicSharedMemorySize,
                         GEMM_SMEM_BYTES);
    cudaFuncSetAttribute(ffn_gemm_mma<2>, cudaFuncAttributeMaxDynamicSharedMemorySize,
                         GEMM_SMEM_BYTES);

    // Router + fused x->fp16 conversion
    dim3 gp(BB, 8);
    pool_split_kernel<<<gp, 256>>>(x);
    router_final_kernel<<<BB, 256>>>(Wp, bp, probs_out, expert_out);

    // Weight transpose + fp16 convert
    {
        dim3 gt1(HH / 32, DD / 32, EE);   // W1 [K=512][N=2048] -> [2048][512]
        transpose_cvt_kernel<<<gt1, dim3(32, 8)>>>(W1, 0, DD, HH);
        dim3 gt2(DD / 32, HH / 32, EE);   // W2 [K=2048][N=512] -> [512][2048]
        transpose_cvt_kernel<<<gt2, dim3(32, 8)>>>(W2, 1, HH, DD);
    }

    // GEMM1: h = relu(x @ W1[e] + b1[e])   M=512, N=2048, K=512
    dim3 g1(HH / 128, TT / 256, BB);      // (16, 2, 32)
    ffn_gemm_mma<1><<<g1, 256, GEMM_SMEM_BYTES>>>(b1, nullptr);

    // GEMM2: out = h @ W2[e] + b2[e]       M=512, N=512, K=2048
    dim3 g2(DD / 128, TT / 256, BB);      // (4, 2, 32)
    ffn_gemm_mma<2><<<g2, 256, GEMM_SMEM_BYTES>>>(b2, final_out);
}

// round 8
// speedup vs baseline: 7.0110x; 1.1334x over previous
#include <cuda_runtime.h>
#include <cuda_fp16.h>
#include <math.h>
#include <cstdint>

// Problem constants
#define BB 32
#define TT 512
#define DD 512
#define EE 8
#define HH 2048

// ---------------------------------------------------------------------------
// Device-global scratch (allocation-free)
// ---------------------------------------------------------------------------
__device__ int   g_expert[BB];
__device__ float g_pool_part[BB][8][DD];
__device__ __half g_x16[(size_t)BB * TT * DD];          // x as fp16
__device__ __half g_w1t[(size_t)EE * HH * DD];          // W1^T : [E][H][D] fp16
__device__ __half g_w2t[(size_t)EE * DD * HH];          // W2^T : [E][D][H] fp16
__device__ __half g_h16[(size_t)BB * TT * HH];          // hidden as fp16

// ---------------------------------------------------------------------------
// Baseline-PTX helpers (sm_80-level features only; compiles at .target sm_103)
// ---------------------------------------------------------------------------
#define SWZ(bo) ((bo) ^ (((bo) >> 3) & 0x70))

#define CP_COMMIT() asm volatile("cp.async.commit_group;" ::: "memory")
#define CP_WAIT(n)  asm volatile("cp.async.wait_group %0;" :: "n"(n) : "memory")

__device__ __forceinline__ uint32_t smem_to_u32(const void* smem_ptr) {
    uint32_t addr;
    asm("{ .reg .u64 tmp; cvta.to.shared.u64 tmp, %1; cvt.u32.u64 %0, tmp; }"
        : "=r"(addr) : "l"(smem_ptr));
    return addr;
}

__device__ __forceinline__ void ldsm4(uint32_t* r, uint32_t addr) {
    asm volatile("ldmatrix.sync.aligned.m8n8.x4.shared.b16 {%0,%1,%2,%3}, [%4];"
                 : "=r"(r[0]), "=r"(r[1]), "=r"(r[2]), "=r"(r[3]) : "r"(addr));
}

__device__ __forceinline__ void mma16816(float* c, const uint32_t* a, const uint32_t* b) {
    asm volatile(
        "mma.sync.aligned.m16n8k16.row.col.f32.f16.f16.f32 "
        "{%0,%1,%2,%3}, {%4,%5,%6,%7}, {%8,%9}, {%0,%1,%2,%3};"
        : "+f"(c[0]), "+f"(c[1]), "+f"(c[2]), "+f"(c[3])
        : "r"(a[0]), "r"(a[1]), "r"(a[2]), "r"(a[3]), "r"(b[0]), "r"(b[1]));
}

// cp.async one ROWSx64(fp16) tile (128B rows, SW128-swizzled). 256 threads.
template<int ROWS>
__device__ __forceinline__ void cpa_tile(uint32_t smem_tile,
                                         const __half* __restrict__ src,
                                         int row0, int k0, int ld, int tid) {
    const char* gbase = (const char*)(src + (size_t)row0 * ld + k0);
    const size_t rs = (size_t)ld * 2;
    #pragma unroll
    for (int j = 0; j < ROWS / 32; ++j) {
        const int linear = j * 256 + tid;      // ROWS*8 chunks of 16B
        const int row = linear >> 3;
        const int c16 = linear & 7;
        const uint32_t bo = (uint32_t)(row * 128 + c16 * 16);
        const uint32_t dst = smem_tile + SWZ(bo);
        const void* g = gbase + (size_t)row * rs + (size_t)c16 * 16;
        asm volatile("cp.async.cg.shared.global [%0], [%1], 16;"
                     :: "r"(dst), "l"(g) : "memory");
    }
}

// ---------------------------------------------------------------------------
// Fused preprocessing (all independent work, one launch):
//   blocks [0, 256)            : partial mean-pool + x -> fp16
//   blocks [256, 256+4096)     : W1 transpose tiles (K=512 -> [H][D])
//   blocks [256+4096, +4096)   : W2 transpose tiles (K=2048 -> [D][H])
// 256 threads per block.
// ---------------------------------------------------------------------------
__device__ __forceinline__ void transpose_tile64(const float* __restrict__ We,
                                                 __half* __restrict__ The,
                                                 int K, int N, int k0, int n0,
                                                 float (*tile)[33], int tid) {
    const int tx = tid & 31, ty = tid >> 5;
    // Load 64(k) x 32(n): each warp-row reads 128B contiguous
    #pragma unroll
    for (int i = 0; i < 8; ++i) {
        const int kk = ty + i * 8;
        tile[kk][tx] = We[(size_t)(k0 + kk) * N + n0 + tx];
    }
    __syncthreads();
    // Store: per n, 64 contiguous k as __half2 -> 128B contiguous per warp-row
    #pragma unroll
    for (int i = 0; i < 4; ++i) {
        const int nn = i * 8 + ty;
        const int n = n0 + nn;
        __half2 v = __floats2half2_rn(tile[tx * 2][nn], tile[tx * 2 + 1][nn]);
        *(__half2*)(The + (size_t)n * K + k0 + tx * 2) = v;
    }
}

__global__ void preproc_kernel(const float* __restrict__ x,
                               const float* __restrict__ W1,
                               const float* __restrict__ W2) {
    __shared__ float tile[64][33];
    const int bid = blockIdx.x;
    const int tid = threadIdx.x;

    if (bid < 256) {
        // ---- pool + x->fp16 ----
        const int b = bid >> 3, ch = bid & 7;
        const float2* xb = (const float2*)(x + (size_t)b * TT * DD);
        __half2* xo = (__half2*)(g_x16 + (size_t)b * TT * DD);
        float2 s = make_float2(0.f, 0.f);
        const int t0 = ch * 64;
        #pragma unroll 4
        for (int t = t0; t < t0 + 64; ++t) {
            float2 v = xb[(size_t)t * 256 + tid];
            s.x += v.x; s.y += v.y;
            xo[(size_t)t * 256 + tid] = __floats2half2_rn(v.x, v.y);
        }
        g_pool_part[b][ch][tid * 2]     = s.x;
        g_pool_part[b][ch][tid * 2 + 1] = s.y;
    } else if (bid < 256 + 4096) {
        // ---- W1 [K=512][N=2048] -> g_w1t [2048][512] ----
        const int t = bid - 256;
        const int e = t >> 9;               // / 512
        const int r = t & 511;
        const int k0 = (r >> 6) * 64;       // 8 k-tiles
        const int n0 = (r & 63) * 32;       // 64 n-tiles
        transpose_tile64(W1 + (size_t)e * DD * HH,
                         g_w1t + (size_t)e * HH * DD, DD, HH, k0, n0, tile, tid);
    } else {
        // ---- W2 [K=2048][N=512] -> g_w2t [512][2048] ----
        const int t = bid - 256 - 4096;
        const int e = t >> 9;
        const int r = t & 511;
        const int k0 = (r >> 4) * 64;       // 32 k-tiles
        const int n0 = (r & 15) * 32;       // 16 n-tiles
        transpose_tile64(W2 + (size_t)e * HH * DD,
                         g_w2t + (size_t)e * DD * HH, HH, DD, k0, n0, tile, tid);
    }
}

// ---------------------------------------------------------------------------
// Router: reduce + logits + softmax + argmax. grid B, 256 threads.
// ---------------------------------------------------------------------------
__global__ void router_final_kernel(const float* __restrict__ Wp,
                                    const float* __restrict__ bp,
                                    float* __restrict__ probs_out,
                                    float* __restrict__ expert_out) {
    const int b = blockIdx.x, tid = threadIdx.x;
    __shared__ float pooled[DD];
    __shared__ float logits[EE];

    for (int d = tid; d < DD; d += 256) {
        float s = 0.f;
        #pragma unroll
        for (int ch = 0; ch < 8; ++ch) s += g_pool_part[b][ch][d];
        pooled[d] = s * (1.0f / (float)TT);
    }
    __syncthreads();

    const int w = tid >> 5, lane = tid & 31;
    if (w < EE) {
        float acc = 0.f;
        for (int d = lane; d < DD; d += 32) acc += pooled[d] * Wp[d * EE + w];
        #pragma unroll
        for (int o = 16; o > 0; o >>= 1) acc += __shfl_down_sync(0xffffffffu, acc, o);
        if (lane == 0) logits[w] = acc + bp[w];
    }
    __syncthreads();

    if (tid == 0) {
        float m = logits[0]; int arg = 0;
        #pragma unroll
        for (int e = 1; e < EE; ++e) if (logits[e] > m) { m = logits[e]; arg = e; }
        float ex[EE], sum = 0.f;
        #pragma unroll
        for (int e = 0; e < EE; ++e) { ex[e] = expf(logits[e] - m); sum += ex[e]; }
        const float inv = 1.0f / sum;
        #pragma unroll
        for (int e = 0; e < EE; ++e) probs_out[b * EE + e] = ex[e] * inv;
        expert_out[b] = (float)arg;
        g_expert[b]   = arg;
    }
}

// ---------------------------------------------------------------------------
// fp16 GEMM on mma.sync.m16n8k16:
//   C[256,128] = A[256,K] @ B[128,K]^T   (B stored [N][K] K-major)
// PHASE 1: A=x16(K=512),  B=W1t, epi: bias+relu -> fp16 -> g_h16
// PHASE 2: A=h16(K=2048), B=W2t, epi: bias -> f32 out
// 256 threads = 8 warps (4 M x 2 N), warp tile 64x64, acc 128 regs/thread.
// SMEM/stage: A 32KB + B 16KB = 48KB; 4-stage ring, prefetch distance 2,
// ONE __syncthreads per chunk (trailing barrier provably redundant at dist 2).
// ---------------------------------------------------------------------------
#define STAGE_BYTES 49152
#define A_OFF  0
#define B_OFF  32768
#define GEMM_SMEM_BYTES (4 * STAGE_BYTES)

template<int PHASE>
__global__ void __launch_bounds__(256, 1)
ffn_gemm_mma(const float* __restrict__ bias_all, float* __restrict__ outf)
{
    constexpr int KTOT = (PHASE == 1) ? DD : HH;       // 512 / 2048
    constexpr int NTOT = (PHASE == 1) ? HH : DD;       // 2048 / 512
    constexpr int NCH  = KTOT / 64;                    // 8 / 32

    extern __shared__ char smem[];
    const uint32_t smem_u32 = smem_to_u32(smem);
    const int tid  = threadIdx.x;
    const int wid  = tid >> 5;
    const int lane = tid & 31;

    const int b  = blockIdx.z;
    const int e  = g_expert[b];
    const int m0 = blockIdx.y * 256;
    const int n0 = blockIdx.x * 128;

    const __half *A16, *Bp;
    if (PHASE == 1) {
        A16 = g_x16 + (size_t)b * TT * DD;
        Bp  = g_w1t + (size_t)e * HH * DD;
    } else {
        A16 = g_h16 + (size_t)b * TT * HH;
        Bp  = g_w2t + (size_t)e * DD * HH;
    }
    const float* bias = bias_all + (size_t)e * NTOT;

    const int wm0 = (wid & 3) * 64;       // warp M origin in CTA tile (4 tiles)
    const int wn0 = (wid >> 2) * 64;      // warp N origin in CTA tile (2 tiles)

    // ldmatrix per-lane address components (SW128 swizzle folded in)
    const int aRow = wm0 + (lane & 15);
    const uint32_t aOff  = (uint32_t)aRow * 128u;
    const uint32_t aSw   = ((uint32_t)aRow & 7u) << 4;
    const uint32_t aHalf = ((uint32_t)(lane >> 4)) * 16u;

    const int bRow = wn0 + ((lane >> 4) * 8) + (lane & 7);
    const uint32_t bOff  = (uint32_t)bRow * 128u;
    const uint32_t bSw   = ((uint32_t)bRow & 7u) << 4;
    const uint32_t bHalf = ((uint32_t)((lane >> 3) & 1)) * 16u;

    float acc[4][8][4];
    #pragma unroll
    for (int mi = 0; mi < 4; ++mi)
        #pragma unroll
        for (int ni = 0; ni < 8; ++ni)
            #pragma unroll
            for (int r = 0; r < 4; ++r) acc[mi][ni][r] = 0.f;

    // Prologue: load chunks 0 and 1 into ring slots 0, 1
    cpa_tile<256>(smem_u32 + 0 * STAGE_BYTES + A_OFF, A16, m0, 0, KTOT, tid);
    cpa_tile<128>(smem_u32 + 0 * STAGE_BYTES + B_OFF, Bp,  n0, 0, KTOT, tid);
    CP_COMMIT();
    cpa_tile<256>(smem_u32 + 1 * STAGE_BYTES + A_OFF, A16, m0, 64, KTOT, tid);
    cpa_tile<128>(smem_u32 + 1 * STAGE_BYTES + B_OFF, Bp,  n0, 64, KTOT, tid);
    CP_COMMIT();

    #pragma unroll 2
    for (int c = 0; c < NCH; ++c) {
        const int slot = c & 3;
        if (c + 2 < NCH) {
            const int ps = (c + 2) & 3;
            const uint32_t st = smem_u32 + ps * STAGE_BYTES;
            const int k0 = (c + 2) * 64;
            cpa_tile<256>(st + A_OFF, A16, m0, k0, KTOT, tid);
            cpa_tile<128>(st + B_OFF, Bp,  n0, k0, KTOT, tid);
            CP_COMMIT();
            CP_WAIT(2);
        } else if (c + 1 < NCH) {
            CP_WAIT(1);
        } else {
            CP_WAIT(0);
        }
        __syncthreads();

        const uint32_t stage = smem_u32 + slot * STAGE_BYTES;
        const uint32_t tA = stage + A_OFF;
        const uint32_t tB = stage + B_OFF;

        #pragma unroll
        for (int ks = 0; ks < 4; ++ks) {
            const uint32_t colA = ((uint32_t)(ks * 32) + aHalf) ^ aSw;
            const uint32_t colB = ((uint32_t)(ks * 32) + bHalf) ^ bSw;

            uint32_t a[4][4];
            #pragma unroll
            for (int mi = 0; mi < 4; ++mi)
                ldsm4(a[mi], tA + aOff + colA + mi * 2048);

            uint32_t bfrag[8][2];
            #pragma unroll
            for (int j = 0; j < 4; ++j) {
                uint32_t r[4];
                ldsm4(r, tB + bOff + colB + j * 2048);
                bfrag[2 * j][0] = r[0]; bfrag[2 * j][1] = r[1];
                bfrag[2 * j + 1][0] = r[2]; bfrag[2 * j + 1][1] = r[3];
            }

            #pragma unroll
            for (int mi = 0; mi < 4; ++mi)
                #pragma unroll
                for (int ni = 0; ni < 8; ++ni)
                    mma16816(acc[mi][ni], a[mi], bfrag[ni]);
        }
        // no trailing __syncthreads: 4-slot ring @ distance 2 makes the next
        // write to this slot ordered by the leading barrier of iteration c+1.
    }

    // Epilogue. c-frag: c0 (r, col), c1 (r, col+1), c2 (r+8, col), c3 (r+8, col+1)
    const int grow0 = m0 + wm0 + (lane >> 2);
    const int gcol0 = n0 + wn0 + (lane & 3) * 2;

    #pragma unroll
    for (int mi = 0; mi < 4; ++mi) {
        #pragma unroll
        for (int ni = 0; ni < 8; ++ni) {
            const int col = gcol0 + ni * 8;
            const float2 bv = *(const float2*)(bias + col);
            const int r0 = grow0 + mi * 16;
            const int r1 = r0 + 8;

            if (PHASE == 1) {
                float v0 = fmaxf(acc[mi][ni][0] + bv.x, 0.f);
                float v1 = fmaxf(acc[mi][ni][1] + bv.y, 0.f);
                float v2 = fmaxf(acc[mi][ni][2] + bv.x, 0.f);
                float v3 = fmaxf(acc[mi][ni][3] + bv.y, 0.f);
                const size_t base0 = ((size_t)b * TT + r0) * HH + col;
                const size_t base1 = ((size_t)b * TT + r1) * HH + col;
                *(__half2*)(g_h16 + base0) = __floats2half2_rn(v0, v1);
                *(__half2*)(g_h16 + base1) = __floats2half2_rn(v2, v3);
            } else {
                float2 o0, o1;
                o0.x = acc[mi][ni][0] + bv.x; o0.y = acc[mi][ni][1] + bv.y;
                o1.x = acc[mi][ni][2] + bv.x; o1.y = acc[mi][ni][3] + bv.y;
                float* op0 = outf + ((size_t)b * TT + r0) * DD + col;
                float* op1 = outf + ((size_t)b * TT + r1) * DD + col;
                *(float2*)op0 = o0;
                *(float2*)op1 = o1;
            }
        }
    }
}

// ---------------------------------------------------------------------------
// Launch. Output layout (float32): final [B*T*D] | probs [B*E] | expert [B]
// ---------------------------------------------------------------------------
extern "C" void kernel_launch(void* const* d_in, const int* in_sizes, int n_in,
                              void* d_out, int out_size)
{
    const float* x  = (const float*)d_in[0];
    const float* Wp = (const float*)d_in[1];
    const float* bp = (const float*)d_in[2];
    const float* W1 = (const float*)d_in[3];
    const float* b1 = (const float*)d_in[4];
    const float* W2 = (const float*)d_in[5];
    const float* b2 = (const float*)d_in[6];

    float* out        = (float*)d_out;
    float* final_out  = out;
    float* probs_out  = out + (size_t)BB * TT * DD;
    float* expert_out = probs_out + (size_t)BB * EE;

    cudaFuncSetAttribute(ffn_gemm_mma<1>, cudaFuncAttributeMaxDynamicSharedMemorySize,
                         GEMM_SMEM_BYTES);
    cudaFuncSetAttribute(ffn_gemm_mma<2>, cudaFuncAttributeMaxDynamicSharedMemorySize,
                         GEMM_SMEM_BYTES);

    // Fused preprocessing: pool + x->fp16 + both weight transposes (one launch)
    preproc_kernel<<<256 + 4096 + 4096, 256>>>(x, W1, W2);
    // Router (needs pool partials)
    router_final_kernel<<<BB, 256>>>(Wp, bp, probs_out, expert_out);

    // GEMM1: h = relu(x @ W1[e] + b1[e])   M=512, N=2048, K=512
    dim3 g1(HH / 128, TT / 256, BB);      // (16, 2, 32)
    ffn_gemm_mma<1><<<g1, 256, GEMM_SMEM_BYTES>>>(b1, nullptr);

    // GEMM2: out = h @ W2[e] + b2[e]       M=512, N=512, K=2048
    dim3 g2(DD / 128, TT / 256, BB);      // (4, 2, 32)
    ffn_gemm_mma<2><<<g2, 256, GEMM_SMEM_BYTES>>>(b2, final_out);
}

// round 10
// speedup vs baseline: 7.1579x; 1.0210x over previous
#include <cuda_runtime.h>
#include <cuda_fp16.h>
#include <math.h>
#include <cstdint>

// Problem constants
#define BB 32
#define TT 512
#define DD 512
#define EE 8
#define HH 2048

// ---------------------------------------------------------------------------
// Device-global scratch (allocation-free)
// ---------------------------------------------------------------------------
__device__ int   g_expert[BB];
__device__ float g_pool_part[BB][8][DD];
__device__ __half g_x16[(size_t)BB * TT * DD];          // x as fp16
__device__ __half g_w1t[(size_t)EE * HH * DD];          // W1^T : [E][H][D] fp16
__device__ __half g_w2t[(size_t)EE * DD * HH];          // W2^T : [E][D][H] fp16
__device__ __half g_h16[(size_t)BB * TT * HH];          // hidden as fp16

// ---------------------------------------------------------------------------
// Baseline-PTX helpers (sm_80-level features only; compiles at .target sm_103)
// ---------------------------------------------------------------------------
#define SWZ(bo) ((bo) ^ (((bo) >> 3) & 0x70))

#define CP_COMMIT() asm volatile("cp.async.commit_group;" ::: "memory")
#define CP_WAIT(n)  asm volatile("cp.async.wait_group %0;" :: "n"(n) : "memory")

__device__ __forceinline__ uint32_t smem_to_u32(const void* smem_ptr) {
    uint32_t addr;
    asm("{ .reg .u64 tmp; cvta.to.shared.u64 tmp, %1; cvt.u32.u64 %0, tmp; }"
        : "=r"(addr) : "l"(smem_ptr));
    return addr;
}

__device__ __forceinline__ void ldsm4(uint32_t* r, uint32_t addr) {
    asm volatile("ldmatrix.sync.aligned.m8n8.x4.shared.b16 {%0,%1,%2,%3}, [%4];"
                 : "=r"(r[0]), "=r"(r[1]), "=r"(r[2]), "=r"(r[3]) : "r"(addr));
}

__device__ __forceinline__ void mma16816(float* c, const uint32_t* a, const uint32_t* b) {
    asm volatile(
        "mma.sync.aligned.m16n8k16.row.col.f32.f16.f16.f32 "
        "{%0,%1,%2,%3}, {%4,%5,%6,%7}, {%8,%9}, {%0,%1,%2,%3};"
        : "+f"(c[0]), "+f"(c[1]), "+f"(c[2]), "+f"(c[3])
        : "r"(a[0]), "r"(a[1]), "r"(a[2]), "r"(a[3]), "r"(b[0]), "r"(b[1]));
}

// cp.async one ROWSx64(fp16) tile (128B rows, SW128-swizzled). 128 threads.
template<int ROWS>
__device__ __forceinline__ void cpa_tile(uint32_t smem_tile,
                                         const __half* __restrict__ src,
                                         int row0, int k0, int ld, int tid) {
    const char* gbase = (const char*)(src + (size_t)row0 * ld + k0);
    const size_t rs = (size_t)ld * 2;
    #pragma unroll
    for (int j = 0; j < ROWS / 16; ++j) {
        const int linear = j * 128 + tid;      // ROWS*8 chunks of 16B
        const int row = linear >> 3;
        const int c16 = linear & 7;
        const uint32_t bo = (uint32_t)(row * 128 + c16 * 16);
        const uint32_t dst = smem_tile + SWZ(bo);
        const void* g = gbase + (size_t)row * rs + (size_t)c16 * 16;
        asm volatile("cp.async.cg.shared.global [%0], [%1], 16;"
                     :: "r"(dst), "l"(g) : "memory");
    }
}

// ---------------------------------------------------------------------------
// Fused preprocessing (all independent work, one launch):
//   blocks [0, 256)            : partial mean-pool + x -> fp16
//   blocks [256, 256+4096)     : W1 transpose tiles (K=512 -> [H][D])
//   blocks [256+4096, +4096)   : W2 transpose tiles (K=2048 -> [D][H])
// 256 threads per block.
// ---------------------------------------------------------------------------
__device__ __forceinline__ void transpose_tile64(const float* __restrict__ We,
                                                 __half* __restrict__ The,
                                                 int K, int N, int k0, int n0,
                                                 float (*tile)[33], int tid) {
    const int tx = tid & 31, ty = tid >> 5;
    #pragma unroll
    for (int i = 0; i < 8; ++i) {
        const int kk = ty + i * 8;
        tile[kk][tx] = We[(size_t)(k0 + kk) * N + n0 + tx];
    }
    __syncthreads();
    #pragma unroll
    for (int i = 0; i < 4; ++i) {
        const int nn = i * 8 + ty;
        const int n = n0 + nn;
        __half2 v = __floats2half2_rn(tile[tx * 2][nn], tile[tx * 2 + 1][nn]);
        *(__half2*)(The + (size_t)n * K + k0 + tx * 2) = v;
    }
}

__global__ void preproc_kernel(const float* __restrict__ x,
                               const float* __restrict__ W1,
                               const float* __restrict__ W2) {
    __shared__ float tile[64][33];
    const int bid = blockIdx.x;
    const int tid = threadIdx.x;

    if (bid < 256) {
        const int b = bid >> 3, ch = bid & 7;
        const float2* xb = (const float2*)(x + (size_t)b * TT * DD);
        __half2* xo = (__half2*)(g_x16 + (size_t)b * TT * DD);
        float2 s = make_float2(0.f, 0.f);
        const int t0 = ch * 64;
        #pragma unroll 4
        for (int t = t0; t < t0 + 64; ++t) {
            float2 v = xb[(size_t)t * 256 + tid];
            s.x += v.x; s.y += v.y;
            xo[(size_t)t * 256 + tid] = __floats2half2_rn(v.x, v.y);
        }
        g_pool_part[b][ch][tid * 2]     = s.x;
        g_pool_part[b][ch][tid * 2 + 1] = s.y;
    } else if (bid < 256 + 4096) {
        const int t = bid - 256;
        const int e = t >> 9;
        const int r = t & 511;
        const int k0 = (r >> 6) * 64;
        const int n0 = (r & 63) * 32;
        transpose_tile64(W1 + (size_t)e * DD * HH,
                         g_w1t + (size_t)e * HH * DD, DD, HH, k0, n0, tile, tid);
    } else {
        const int t = bid - 256 - 4096;
        const int e = t >> 9;
        const int r = t & 511;
        const int k0 = (r >> 4) * 64;
        const int n0 = (r & 15) * 32;
        transpose_tile64(W2 + (size_t)e * HH * DD,
                         g_w2t + (size_t)e * DD * HH, HH, DD, k0, n0, tile, tid);
    }
}

// ---------------------------------------------------------------------------
// Router: reduce + logits + softmax + argmax. grid B, 256 threads.
// ---------------------------------------------------------------------------
__global__ void router_final_kernel(const float* __restrict__ Wp,
                                    const float* __restrict__ bp,
                                    float* __restrict__ probs_out,
                                    float* __restrict__ expert_out) {
    const int b = blockIdx.x, tid = threadIdx.x;
    __shared__ float pooled[DD];
    __shared__ float logits[EE];

    for (int d = tid; d < DD; d += 256) {
        float s = 0.f;
        #pragma unroll
        for (int ch = 0; ch < 8; ++ch) s += g_pool_part[b][ch][d];
        pooled[d] = s * (1.0f / (float)TT);
    }
    __syncthreads();

    const int w = tid >> 5, lane = tid & 31;
    if (w < EE) {
        float acc = 0.f;
        for (int d = lane; d < DD; d += 32) acc += pooled[d] * Wp[d * EE + w];
        #pragma unroll
        for (int o = 16; o > 0; o >>= 1) acc += __shfl_down_sync(0xffffffffu, acc, o);
        if (lane == 0) logits[w] = acc + bp[w];
    }
    __syncthreads();

    if (tid == 0) {
        float m = logits[0]; int arg = 0;
        #pragma unroll
        for (int e = 1; e < EE; ++e) if (logits[e] > m) { m = logits[e]; arg = e; }
        float ex[EE], sum = 0.f;
        #pragma unroll
        for (int e = 0; e < EE; ++e) { ex[e] = expf(logits[e] - m); sum += ex[e]; }
        const float inv = 1.0f / sum;
        #pragma unroll
        for (int e = 0; e < EE; ++e) probs_out[b * EE + e] = ex[e] * inv;
        expert_out[b] = (float)arg;
        g_expert[b]   = arg;
    }
}

// ---------------------------------------------------------------------------
// fp16 GEMM on mma.sync.m16n8k16:
//   C[128,128] = A[128,K] @ B[128,K]^T   (B stored [N][K] K-major)
// PHASE 1: A=x16(K=512),  B=W1t, epi: bias+relu -> fp16 -> g_h16
// PHASE 2: A=h16(K=2048), B=W2t, epi: bias -> f32 out
// 128 threads = 4 warps (2 M x 2 N), warp tile 64x64, acc 128 regs/thread.
// SMEM/stage: A 16KB + B 16KB = 32KB; 3-stage ring = 96KB -> 2 CTAs/SM.
// Single barrier per chunk: prefetch issued AFTER the barrier, so the slot
// being overwritten ((c+2)%3 == slot of c-1) is provably drained.
// ---------------------------------------------------------------------------
#define STAGE_BYTES 32768
#define A_OFF  0
#define B_OFF  16384
#define GEMM_SMEM_BYTES (3 * STAGE_BYTES)

template<int PHASE>
__global__ void __launch_bounds__(128, 2)
ffn_gemm_mma(const float* __restrict__ bias_all, float* __restrict__ outf)
{
    constexpr int KTOT = (PHASE == 1) ? DD : HH;       // 512 / 2048
    constexpr int NTOT = (PHASE == 1) ? HH : DD;       // 2048 / 512
    constexpr int NCH  = KTOT / 64;                    // 8 / 32

    extern __shared__ char smem[];
    const uint32_t smem_u32 = smem_to_u32(smem);
    const int tid  = threadIdx.x;
    const int wid  = tid >> 5;
    const int lane = tid & 31;

    const int b  = blockIdx.z;
    const int e  = g_expert[b];
    const int m0 = blockIdx.y * 128;
    const int n0 = blockIdx.x * 128;

    const __half *A16, *Bp;
    if (PHASE == 1) {
        A16 = g_x16 + (size_t)b * TT * DD;
        Bp  = g_w1t + (size_t)e * HH * DD;
    } else {
        A16 = g_h16 + (size_t)b * TT * HH;
        Bp  = g_w2t + (size_t)e * DD * HH;
    }
    const float* bias = bias_all + (size_t)e * NTOT;

    const int wm0 = (wid & 1) * 64;       // warp M origin (2 tiles)
    const int wn0 = (wid >> 1) * 64;      // warp N origin (2 tiles)

    // ldmatrix per-lane address components (SW128 swizzle folded in)
    const int aRow = wm0 + (lane & 15);
    const uint32_t aOff  = (uint32_t)aRow * 128u;
    const uint32_t aSw   = ((uint32_t)aRow & 7u) << 4;
    const uint32_t aHalf = ((uint32_t)(lane >> 4)) * 16u;

    const int bRow = wn0 + ((lane >> 4) * 8) + (lane & 7);
    const uint32_t bOff  = (uint32_t)bRow * 128u;
    const uint32_t bSw   = ((uint32_t)bRow & 7u) << 4;
    const uint32_t bHalf = ((uint32_t)((lane >> 3) & 1)) * 16u;

    float acc[4][8][4];
    #pragma unroll
    for (int mi = 0; mi < 4; ++mi)
        #pragma unroll
        for (int ni = 0; ni < 8; ++ni)
            #pragma unroll
            for (int r = 0; r < 4; ++r) acc[mi][ni][r] = 0.f;

    // Prologue: chunks 0,1 -> slots 0,1
    cpa_tile<128>(smem_u32 + 0 * STAGE_BYTES + A_OFF, A16, m0, 0, KTOT, tid);
    cpa_tile<128>(smem_u32 + 0 * STAGE_BYTES + B_OFF, Bp,  n0, 0, KTOT, tid);
    CP_COMMIT();
    cpa_tile<128>(smem_u32 + 1 * STAGE_BYTES + A_OFF, A16, m0, 64, KTOT, tid);
    cpa_tile<128>(smem_u32 + 1 * STAGE_BYTES + B_OFF, Bp,  n0, 64, KTOT, tid);
    CP_COMMIT();

    int slot = 0;
    #pragma unroll 2
    for (int c = 0; c < NCH; ++c) {
        if (c + 1 < NCH) { CP_WAIT(1); } else { CP_WAIT(0); }
        __syncthreads();

        if (c + 2 < NCH) {
            const int ps = (slot + 2 >= 3) ? slot - 1 : slot + 2;  // (c+2)%3
            const uint32_t st = smem_u32 + ps * STAGE_BYTES;
            const int k0 = (c + 2) * 64;
            cpa_tile<128>(st + A_OFF, A16, m0, k0, KTOT, tid);
            cpa_tile<128>(st + B_OFF, Bp,  n0, k0, KTOT, tid);
            CP_COMMIT();
        }

        const uint32_t stage = smem_u32 + slot * STAGE_BYTES;
        const uint32_t tA = stage + A_OFF;
        const uint32_t tB = stage + B_OFF;

        #pragma unroll
        for (int ks = 0; ks < 4; ++ks) {
            const uint32_t colA = ((uint32_t)(ks * 32) + aHalf) ^ aSw;
            const uint32_t colB = ((uint32_t)(ks * 32) + bHalf) ^ bSw;

            uint32_t a[4][4];
            #pragma unroll
            for (int mi = 0; mi < 4; ++mi)
                ldsm4(a[mi], tA + aOff + colA + mi * 2048);

            uint32_t bfrag[8][2];
            #pragma unroll
            for (int j = 0; j < 4; ++j) {
                uint32_t r[4];
                ldsm4(r, tB + bOff + colB + j * 2048);
                bfrag[2 * j][0] = r[0]; bfrag[2 * j][1] = r[1];
                bfrag[2 * j + 1][0] = r[2]; bfrag[2 * j + 1][1] = r[3];
            }

            #pragma unroll
            for (int mi = 0; mi < 4; ++mi)
                #pragma unroll
                for (int ni = 0; ni < 8; ++ni)
                    mma16816(acc[mi][ni], a[mi], bfrag[ni]);
        }

        slot = (slot + 1 >= 3) ? 0 : slot + 1;
    }

    // Epilogue. c-frag: c0 (r, col), c1 (r, col+1), c2 (r+8, col), c3 (r+8, col+1)
    const int grow0 = m0 + wm0 + (lane >> 2);
    const int gcol0 = n0 + wn0 + (lane & 3) * 2;

    #pragma unroll
    for (int mi = 0; mi < 4; ++mi) {
        #pragma unroll
        for (int ni = 0; ni < 8; ++ni) {
            const int col = gcol0 + ni * 8;
            const float2 bv = *(const float2*)(bias + col);
            const int r0 = grow0 + mi * 16;
            const int r1 = r0 + 8;

            if (PHASE == 1) {
                float v0 = fmaxf(acc[mi][ni][0] + bv.x, 0.f);
                float v1 = fmaxf(acc[mi][ni][1] + bv.y, 0.f);
                float v2 = fmaxf(acc[mi][ni][2] + bv.x, 0.f);
                float v3 = fmaxf(acc[mi][ni][3] + bv.y, 0.f);
                const size_t base0 = ((size_t)b * TT + r0) * HH + col;
                const size_t base1 = ((size_t)b * TT + r1) * HH + col;
                *(__half2*)(g_h16 + base0) = __floats2half2_rn(v0, v1);
                *(__half2*)(g_h16 + base1) = __floats2half2_rn(v2, v3);
            } else {
                float2 o0, o1;
                o0.x = acc[mi][ni][0] + bv.x; o0.y = acc[mi][ni][1] + bv.y;
                o1.x = acc[mi][ni][2] + bv.x; o1.y = acc[mi][ni][3] + bv.y;
                float* op0 = outf + ((size_t)b * TT + r0) * DD + col;
                float* op1 = outf + ((size_t)b * TT + r1) * DD + col;
                *(float2*)op0 = o0;
                *(float2*)op1 = o1;
            }
        }
    }
}

// ---------------------------------------------------------------------------
// Launch. Output layout (float32): final [B*T*D] | probs [B*E] | expert [B]
// ---------------------------------------------------------------------------
extern "C" void kernel_launch(void* const* d_in, const int* in_sizes, int n_in,
                              void* d_out, int out_size)
{
    const float* x  = (const float*)d_in[0];
    const float* Wp = (const float*)d_in[1];
    const float* bp = (const float*)d_in[2];
    const float* W1 = (const float*)d_in[3];
    const float* b1 = (const float*)d_in[4];
    const float* W2 = (const float*)d_in[5];
    const float* b2 = (const float*)d_in[6];

    float* out        = (float*)d_out;
    float* final_out  = out;
    float* probs_out  = out + (size_t)BB * TT * DD;
    float* expert_out = probs_out + (size_t)BB * EE;

    cudaFuncSetAttribute(ffn_gemm_mma<1>, cudaFuncAttributeMaxDynamicSharedMemorySize,
                         GEMM_SMEM_BYTES);
    cudaFuncSetAttribute(ffn_gemm_mma<2>, cudaFuncAttributeMaxDynamicSharedMemorySize,
                         GEMM_SMEM_BYTES);

    // Fused preprocessing: pool + x->fp16 + both weight transposes (one launch)
    preproc_kernel<<<256 + 4096 + 4096, 256>>>(x, W1, W2);
    // Router (needs pool partials)
    router_final_kernel<<<BB, 256>>>(Wp, bp, probs_out, expert_out);

    // GEMM1: h = relu(x @ W1[e] + b1[e])   M=512, N=2048, K=512
    dim3 g1(HH / 128, TT / 128, BB);      // (16, 4, 32)
    ffn_gemm_mma<1><<<g1, 128, GEMM_SMEM_BYTES>>>(b1, nullptr);

    // GEMM2: out = h @ W2[e] + b2[e]       M=512, N=512, K=2048
    dim3 g2(DD / 128, TT / 128, BB);      // (4, 4, 32)
    ffn_gemm_mma<2><<<g2, 128, GEMM_SMEM_BYTES>>>(b2, final_out);
}